// round 4
// baseline (speedup 1.0000x reference)
#include <cuda_runtime.h>
#include <math.h>

// ----------------------------------------------------------------------------
// Problem constants
//   T=32, B=32, TB=1024, NA=5, HID=256, FEAT=512, IN_DIM=517, FLAT=3136
// Output layout (22528 floats): logits[1024*5] | v[1024] | hT[32*256] | cT[32*256]
// ----------------------------------------------------------------------------

#define TBn 1024

// Scratch (device globals; no allocation allowed)
__device__ float g_x1[TBn * 32 * 20 * 20];   // conv1 out
__device__ float g_x2[TBn * 64 * 9 * 9];     // conv2 out
__device__ float g_x3[TBn * 3136];           // conv3 out (flatten, C,H,W)
__device__ float g_xs[TBn * 517];            // feat || one-hot
__device__ float g_pre[TBn * 1024];          // x @ W_ih^T + b_ih + b_hh
__device__ float g_whhT[256 * 1024];         // W_hh transposed: [k][4*HID]
__device__ float g_bsum[1024];               // b_ih + b_hh
__device__ float g_wp1T[256 * 64];           // Wp1 transposed [k][64]
__device__ float g_wv1T[256 * 64];           // Wv1 transposed [k][64]
__device__ float g_hs[TBn * 256];            // all h outputs

__device__ __forceinline__ float sigmoidf(float x) { return 1.0f / (1.0f + expf(-x)); }

// ----------------------------------------------------------------------------
// prep: transpose W_hh -> g_whhT, Wp1/Wv1 -> g_wp1T/g_wv1T, bsum
// ----------------------------------------------------------------------------
__global__ void prep_kernel(const float* __restrict__ W_hh,
                            const float* __restrict__ b_ih,
                            const float* __restrict__ b_hh,
                            const float* __restrict__ Wp1,
                            const float* __restrict__ Wv1) {
    int idx = blockIdx.x * blockDim.x + threadIdx.x;
    if (idx < 262144) {
        int j = idx >> 8, k = idx & 255;
        g_whhT[k * 1024 + j] = W_hh[idx];
    }
    if (idx < 16384) {
        int j = idx >> 8, k = idx & 255;
        g_wp1T[k * 64 + j] = Wp1[idx];
        g_wv1T[k * 64 + j] = Wv1[idx];
    }
    if (idx < 1024) g_bsum[idx] = b_ih[idx] + b_hh[idx];
}

// ----------------------------------------------------------------------------
// one-hot columns of xs (cols 512..516)
// ----------------------------------------------------------------------------
__global__ void onehot_kernel(const int* __restrict__ la) {
    int r = blockIdx.x * blockDim.x + threadIdx.x;
    if (r < TBn) {
        int a = la[r];
        float* p = g_xs + r * 517 + 512;
#pragma unroll
        for (int j = 0; j < 5; j++) p[j] = (j == a) ? 1.0f : 0.0f;
    }
}

// ----------------------------------------------------------------------------
// conv1: in (TB,3,84,84)/255, W (32,3,8,8) stride4 -> (TB,32,20,20) relu
// One block per image. 400 threads (one per output pixel), 32 acc each.
// Weights in smem transposed [k][32] with xor swizzle (float4-granule).
// ----------------------------------------------------------------------------
__global__ void conv1_kernel(const float* __restrict__ img,
                             const float* __restrict__ W1,
                             const float* __restrict__ b1) {
    extern __shared__ float sm[];
    float* img_s = sm;           // 21168 floats
    float* wt_s = sm + 21168;    // 6144 floats
    int n = blockIdx.x, tid = threadIdx.x;
    const float* g = img + n * 21168;
    for (int i = tid; i < 21168; i += 400) img_s[i] = g[i] * (1.0f / 255.0f);
    for (int i = tid; i < 6144; i += 400) {
        int oc = i / 192, k = i % 192;
        wt_s[(k * 32 + oc) ^ ((k & 7) << 2)] = W1[i];
    }
    __syncthreads();

    int oy = tid / 20, ox = tid % 20;
    float acc[32];
#pragma unroll
    for (int i = 0; i < 32; i++) acc[i] = 0.0f;
    const float4* w4 = reinterpret_cast<const float4*>(wt_s);

    for (int ic = 0; ic < 3; ic++) {
#pragma unroll
        for (int ky = 0; ky < 8; ky++) {
            const float* row = img_s + ic * 7056 + (oy * 4 + ky) * 84 + ox * 4;
#pragma unroll
            for (int kx = 0; kx < 8; kx++) {
                float v = row[kx];
                int k = (ic * 8 + ky) * 8 + kx;
                int base = k * 8, sw = k & 7;
#pragma unroll
                for (int q = 0; q < 8; q++) {
                    float4 w = w4[(base + q) ^ sw];
                    acc[q * 4 + 0] = fmaf(v, w.x, acc[q * 4 + 0]);
                    acc[q * 4 + 1] = fmaf(v, w.y, acc[q * 4 + 1]);
                    acc[q * 4 + 2] = fmaf(v, w.z, acc[q * 4 + 2]);
                    acc[q * 4 + 3] = fmaf(v, w.w, acc[q * 4 + 3]);
                }
            }
        }
    }
    float* o = g_x1 + n * 12800;
#pragma unroll
    for (int oc = 0; oc < 32; oc++)
        o[oc * 400 + tid] = fmaxf(acc[oc] + b1[oc], 0.0f);
}

// ----------------------------------------------------------------------------
// conv2: (TB,32,20,20) * W(64,32,4,4) s2 -> (TB,64,9,9) relu
// 324 threads: 81 pixels x 4 channel-groups (16 ch each)
// ----------------------------------------------------------------------------
__global__ void conv2_kernel(const float* __restrict__ W2,
                             const float* __restrict__ b2) {
    extern __shared__ float sm[];
    float* img_s = sm;            // 12800
    float* wt_s = sm + 12800;     // 32768
    int n = blockIdx.x, tid = threadIdx.x;
    const float* g = g_x1 + n * 12800;
    for (int i = tid; i < 12800; i += 324) img_s[i] = g[i];
    for (int i = tid; i < 32768; i += 324) {
        int oc = i >> 9, k = i & 511;
        wt_s[(k * 64 + oc) ^ ((k & 7) << 2)] = W2[i];
    }
    __syncthreads();

    int pix = tid % 81, grp = tid / 81;
    int oy = pix / 9, ox = pix % 9;
    float acc[16];
#pragma unroll
    for (int i = 0; i < 16; i++) acc[i] = 0.0f;
    const float4* w4 = reinterpret_cast<const float4*>(wt_s);

    for (int ic = 0; ic < 32; ic++) {
#pragma unroll
        for (int ky = 0; ky < 4; ky++) {
            const float* row = img_s + ic * 400 + (oy * 2 + ky) * 20 + ox * 2;
#pragma unroll
            for (int kx = 0; kx < 4; kx++) {
                float v = row[kx];
                int k = (ic * 4 + ky) * 4 + kx;
                int base = k * 16 + grp * 4, sw = k & 7;
#pragma unroll
                for (int q = 0; q < 4; q++) {
                    float4 w = w4[(base + q) ^ sw];
                    acc[q * 4 + 0] = fmaf(v, w.x, acc[q * 4 + 0]);
                    acc[q * 4 + 1] = fmaf(v, w.y, acc[q * 4 + 1]);
                    acc[q * 4 + 2] = fmaf(v, w.z, acc[q * 4 + 2]);
                    acc[q * 4 + 3] = fmaf(v, w.w, acc[q * 4 + 3]);
                }
            }
        }
    }
    float* o = g_x2 + n * 5184;
#pragma unroll
    for (int q = 0; q < 4; q++)
#pragma unroll
        for (int c = 0; c < 4; c++) {
            int oc = grp * 16 + q * 4 + c;
            o[oc * 81 + pix] = fmaxf(acc[q * 4 + c] + b2[oc], 0.0f);
        }
}

// ----------------------------------------------------------------------------
// conv3: (TB,64,9,9) * W(64,64,3,3) s1 -> (TB,64,7,7) relu -> flatten
// 392 threads: 49 pixels x 8 channel-groups (8 ch each)
// ----------------------------------------------------------------------------
__global__ void conv3_kernel(const float* __restrict__ W3,
                             const float* __restrict__ b3) {
    extern __shared__ float sm[];
    float* img_s = sm;           // 5184
    float* wt_s = sm + 5184;     // 36864
    int n = blockIdx.x, tid = threadIdx.x;
    const float* g = g_x2 + n * 5184;
    for (int i = tid; i < 5184; i += 392) img_s[i] = g[i];
    for (int i = tid; i < 36864; i += 392) {
        int oc = i / 576, k = i % 576;
        wt_s[(k * 64 + oc) ^ ((k & 7) << 2)] = W3[i];
    }
    __syncthreads();

    int pix = tid % 49, grp = tid / 49;
    int oy = pix / 7, ox = pix % 7;
    float acc[8];
#pragma unroll
    for (int i = 0; i < 8; i++) acc[i] = 0.0f;
    const float4* w4 = reinterpret_cast<const float4*>(wt_s);

    for (int ic = 0; ic < 64; ic++) {
#pragma unroll
        for (int ky = 0; ky < 3; ky++) {
            const float* row = img_s + ic * 81 + (oy + ky) * 9 + ox;
#pragma unroll
            for (int kx = 0; kx < 3; kx++) {
                float v = row[kx];
                int k = (ic * 3 + ky) * 3 + kx;
                int base = k * 16 + grp * 2, sw = k & 7;
#pragma unroll
                for (int q = 0; q < 2; q++) {
                    float4 w = w4[(base + q) ^ sw];
                    acc[q * 4 + 0] = fmaf(v, w.x, acc[q * 4 + 0]);
                    acc[q * 4 + 1] = fmaf(v, w.y, acc[q * 4 + 1]);
                    acc[q * 4 + 2] = fmaf(v, w.z, acc[q * 4 + 2]);
                    acc[q * 4 + 3] = fmaf(v, w.w, acc[q * 4 + 3]);
                }
            }
        }
    }
    float* o = g_x3 + n * 3136;
#pragma unroll
    for (int q = 0; q < 2; q++)
#pragma unroll
        for (int c = 0; c < 4; c++) {
            int oc = grp * 8 + q * 4 + c;
            o[oc * 49 + pix] = fmaxf(acc[q * 4 + c] + b3[oc], 0.0f);
        }
}

// ----------------------------------------------------------------------------
// Generic tiled GEMM body: C[M x N] = act(A[M x K] * B[N x K]^T + bias)
// BM=BN=64, BK=16, 256 threads, 4x4 microtile, K-major smem tiles.
// ----------------------------------------------------------------------------
__device__ __forceinline__ void gemm_body(const float* __restrict__ A,
                                          const float* __restrict__ B,
                                          const float* __restrict__ bias,
                                          float* __restrict__ C,
                                          int K, int lda, int ldb, int ldc,
                                          bool relu) {
    __shared__ float As[16][68];
    __shared__ float Bs[16][68];
    int bm = blockIdx.y * 64, bn = blockIdx.x * 64;
    int tid = threadIdx.x;
    int tx = tid & 15, ty = tid >> 4;
    float acc[4][4];
#pragma unroll
    for (int i = 0; i < 4; i++)
#pragma unroll
        for (int j = 0; j < 4; j++) acc[i][j] = 0.0f;

    for (int k0 = 0; k0 < K; k0 += 16) {
        for (int i = tid; i < 64 * 16; i += 256) {
            int m = i >> 4, k = i & 15;
            As[k][m] = (k0 + k < K) ? A[(bm + m) * lda + k0 + k] : 0.0f;
        }
        for (int i = tid; i < 64 * 16; i += 256) {
            int nn = i >> 4, k = i & 15;
            Bs[k][nn] = (k0 + k < K) ? B[(bn + nn) * ldb + k0 + k] : 0.0f;
        }
        __syncthreads();
#pragma unroll
        for (int k = 0; k < 16; k++) {
            float4 av = *reinterpret_cast<const float4*>(&As[k][ty * 4]);
            float4 bv = *reinterpret_cast<const float4*>(&Bs[k][tx * 4]);
            float a_[4] = {av.x, av.y, av.z, av.w};
            float b_[4] = {bv.x, bv.y, bv.z, bv.w};
#pragma unroll
            for (int i = 0; i < 4; i++)
#pragma unroll
                for (int j = 0; j < 4; j++)
                    acc[i][j] = fmaf(a_[i], b_[j], acc[i][j]);
        }
        __syncthreads();
    }
#pragma unroll
    for (int i = 0; i < 4; i++) {
        int row = bm + ty * 4 + i;
#pragma unroll
        for (int j = 0; j < 4; j++) {
            int col = bn + tx * 4 + j;
            float v = acc[i][j] + bias[col];
            if (relu) v = fmaxf(v, 0.0f);
            C[row * ldc + col] = v;
        }
    }
}

// FC: feat = relu(x3 @ Wfc^T + bfc) -> g_xs cols [0,512)
__global__ void gemm_fc_kernel(const float* __restrict__ Wfc,
                               const float* __restrict__ bfc) {
    gemm_body(g_x3, Wfc, bfc, g_xs, 3136, 3136, 3136, 517, true);
}

// pre = xs @ W_ih^T + (b_ih + b_hh) -> g_pre
__global__ void gemm_pre_kernel(const float* __restrict__ W_ih) {
    gemm_body(g_xs, W_ih, g_bsum, g_pre, 517, 517, 517, 1024, false);
}

// ----------------------------------------------------------------------------
// LSTM: 32 blocks (one per batch element), persistent over all 32 timesteps.
// Thread u computes 4 consecutive gate pre-activations (j = 4u..4u+3) via
// coalesced float4 loads of g_whhT[k][j]; gate exchange through smem.
// ----------------------------------------------------------------------------
__global__ void lstm_kernel(const float* __restrict__ done,
                            const float* __restrict__ h0,
                            const float* __restrict__ c0,
                            float* __restrict__ hT,
                            float* __restrict__ cT) {
    __shared__ float h_s[256];
    __shared__ float g_s[1024];
    int b = blockIdx.x, u = threadIdx.x;
    h_s[u] = h0[b * 256 + u];
    float c_reg = c0[b * 256 + u];
    const float4* w4 = reinterpret_cast<const float4*>(g_whhT);
    float4* gs4 = reinterpret_cast<float4*>(g_s);
    __syncthreads();

    for (int t = 0; t < 32; t++) {
        float m = 1.0f - __ldg(&done[(t << 5) + b]);
        float hv = h_s[u] * m;
        c_reg *= m;
        h_s[u] = hv;
        __syncthreads();

        float4 a = *reinterpret_cast<const float4*>(g_pre + (((t << 5) + b) << 10) + (u << 2));
#pragma unroll 8
        for (int k = 0; k < 256; k++) {
            float hk = h_s[k];
            float4 w = __ldg(&w4[k * 256 + u]);
            a.x = fmaf(hk, w.x, a.x);
            a.y = fmaf(hk, w.y, a.y);
            a.z = fmaf(hk, w.z, a.z);
            a.w = fmaf(hk, w.w, a.w);
        }
        gs4[u] = a;
        __syncthreads();

        float gi = sigmoidf(g_s[u]);
        float gf = sigmoidf(g_s[256 + u]);
        float gg = tanhf(g_s[512 + u]);
        float go = sigmoidf(g_s[768 + u]);
        c_reg = gf * c_reg + gi * gg;
        float hn = go * tanhf(c_reg);
        g_hs[(((t << 5) + b) << 8) + u] = hn;
        h_s[u] = hn;
        __syncthreads();
    }
    hT[b * 256 + u] = h_s[u];
    cT[b * 256 + u] = c_reg;
}

// ----------------------------------------------------------------------------
// Heads: logits = tanh(h@Wp1^T+bp1)@Wp2^T+bp2 ; v analogous. One block per row.
// ----------------------------------------------------------------------------
__global__ void heads_kernel(const float* __restrict__ bp1,
                             const float* __restrict__ Wp2,
                             const float* __restrict__ bp2,
                             const float* __restrict__ bv1,
                             const float* __restrict__ Wv2,
                             const float* __restrict__ bv2,
                             float* __restrict__ logits,
                             float* __restrict__ vout) {
    __shared__ float h_s[256];
    __shared__ float hp[64];
    __shared__ float hv[64];
    int r = blockIdx.x, t = threadIdx.x;
    h_s[t] = g_hs[r * 256 + t];
    h_s[t + 128] = g_hs[r * 256 + t + 128];
    __syncthreads();

    if (t < 64) {
        float s = bp1[t];
#pragma unroll 8
        for (int k = 0; k < 256; k++) s = fmaf(h_s[k], g_wp1T[k * 64 + t], s);
        hp[t] = tanhf(s);
    } else {
        int j = t - 64;
        float s = bv1[j];
#pragma unroll 8
        for (int k = 0; k < 256; k++) s = fmaf(h_s[k], g_wv1T[k * 64 + j], s);
        hv[j] = tanhf(s);
    }
    __syncthreads();

    if (t < 5) {
        float s = bp2[t];
#pragma unroll
        for (int k = 0; k < 64; k++) s = fmaf(hp[k], Wp2[t * 64 + k], s);
        logits[r * 5 + t] = s;
    }
    if (t == 8) {
        float s = bv2[0];
#pragma unroll
        for (int k = 0; k < 64; k++) s = fmaf(hv[k], Wv2[k], s);
        vout[r] = s;
    }
}

// ----------------------------------------------------------------------------
// Launch
// ----------------------------------------------------------------------------
extern "C" void kernel_launch(void* const* d_in, const int* in_sizes, int n_in,
                              void* d_out, int out_size) {
    const float* image = (const float*)d_in[0];
    const int* la = (const int*)d_in[1];
    const float* done = (const float*)d_in[2];
    const float* h0 = (const float*)d_in[3];
    const float* c0 = (const float*)d_in[4];
    const float* W1 = (const float*)d_in[5];
    const float* b1 = (const float*)d_in[6];
    const float* W2 = (const float*)d_in[7];
    const float* b2 = (const float*)d_in[8];
    const float* W3 = (const float*)d_in[9];
    const float* b3 = (const float*)d_in[10];
    const float* Wfc = (const float*)d_in[11];
    const float* bfc = (const float*)d_in[12];
    const float* W_ih = (const float*)d_in[13];
    const float* W_hh = (const float*)d_in[14];
    const float* b_ih = (const float*)d_in[15];
    const float* b_hh = (const float*)d_in[16];
    const float* Wp1 = (const float*)d_in[17];
    const float* bp1 = (const float*)d_in[18];
    const float* Wp2 = (const float*)d_in[19];
    const float* bp2 = (const float*)d_in[20];
    const float* Wv1 = (const float*)d_in[21];
    const float* bv1 = (const float*)d_in[22];
    const float* Wv2 = (const float*)d_in[23];
    const float* bv2 = (const float*)d_in[24];

    float* out = (float*)d_out;
    float* o_logits = out;           // 5120
    float* o_v = out + 5120;         // 1024
    float* o_hT = out + 6144;        // 8192
    float* o_cT = out + 14336;       // 8192

    const int SMEM1 = (21168 + 6144) * 4;    // 109248
    const int SMEM2 = (12800 + 32768) * 4;   // 182272
    const int SMEM3 = (5184 + 36864) * 4;    // 168192
    cudaFuncSetAttribute(conv1_kernel, cudaFuncAttributeMaxDynamicSharedMemorySize, SMEM1);
    cudaFuncSetAttribute(conv2_kernel, cudaFuncAttributeMaxDynamicSharedMemorySize, SMEM2);
    cudaFuncSetAttribute(conv3_kernel, cudaFuncAttributeMaxDynamicSharedMemorySize, SMEM3);

    prep_kernel<<<1024, 256>>>(W_hh, b_ih, b_hh, Wp1, Wv1);
    conv1_kernel<<<TBn, 400, SMEM1>>>(image, W1, b1);
    conv2_kernel<<<TBn, 324, SMEM2>>>(W2, b2);
    conv3_kernel<<<TBn, 392, SMEM3>>>(W3, b3);
    gemm_fc_kernel<<<dim3(512 / 64, 1024 / 64), 256>>>(Wfc, bfc);
    onehot_kernel<<<4, 256>>>(la);
    gemm_pre_kernel<<<dim3(1024 / 64, 1024 / 64), 256>>>(W_ih);
    lstm_kernel<<<32, 256>>>(done, h0, c0, o_hT, o_cT);
    heads_kernel<<<TBn, 128>>>(bp1, Wp2, bp2, bv1, Wv2, bv2, o_logits, o_v);
}

// round 6
// speedup vs baseline: 1.2356x; 1.2356x over previous
#include <cuda_runtime.h>
#include <math.h>

// ----------------------------------------------------------------------------
// Problem constants
//   T=32, B=32, TB=1024, NA=5, HID=256, FEAT=512, IN_DIM=517, FLAT=3136
// Output layout (22528 floats): logits[1024*5] | v[1024] | hT[32*256] | cT[32*256]
// ----------------------------------------------------------------------------

#define TBn 1024

// Scratch (device globals; no allocation allowed)
__device__ float g_x1[TBn * 32 * 20 * 20];   // conv1 out
__device__ float g_x2[TBn * 64 * 9 * 9];     // conv2 out
__device__ float g_x3[TBn * 3136];           // conv3 out (flatten, C,H,W)
__device__ float g_xs[TBn * 517];            // feat || one-hot
__device__ float g_pre[TBn * 1024];          // x @ W_ih^T + b_ih + b_hh
__device__ float g_whhT[256 * 1024];         // W_hh transposed: [k][4*HID]
__device__ float g_bsum[1024];               // b_ih + b_hh
__device__ float g_wp1T[256 * 64];           // Wp1 transposed [k][64]
__device__ float g_wv1T[256 * 64];           // Wv1 transposed [k][64]
__device__ float g_hs[TBn * 256];            // all h outputs
// Pre-packed conv weights, transposed to [k][oc] so 8-oc groups are one
// contiguous float4-pair per k.
__device__ float g_w1p[192 * 32];            // conv1 W: [k=ic*64+ky*8+kx][oc]
__device__ float g_w2p[512 * 64];            // conv2 W: [k=ic*16+ky*4+kx][oc]
__device__ float g_w3p[576 * 64];            // conv3 W: [k=ic*9+ky*3+kx][oc]

__device__ __forceinline__ float sigmoidf(float x) { return 1.0f / (1.0f + expf(-x)); }

// ----------------------------------------------------------------------------
// prep: transpose W_hh -> g_whhT, Wp1/Wv1, bsum, pack conv weights
// ----------------------------------------------------------------------------
__global__ void prep_kernel(const float* __restrict__ W_hh,
                            const float* __restrict__ b_ih,
                            const float* __restrict__ b_hh,
                            const float* __restrict__ Wp1,
                            const float* __restrict__ Wv1,
                            const float* __restrict__ W1,
                            const float* __restrict__ W2,
                            const float* __restrict__ W3) {
    int idx = blockIdx.x * blockDim.x + threadIdx.x;
    if (idx < 262144) {
        int j = idx >> 8, k = idx & 255;
        g_whhT[k * 1024 + j] = W_hh[idx];
    }
    if (idx < 16384) {
        int j = idx >> 8, k = idx & 255;
        g_wp1T[k * 64 + j] = Wp1[idx];
        g_wv1T[k * 64 + j] = Wv1[idx];
    }
    if (idx < 1024) g_bsum[idx] = b_ih[idx] + b_hh[idx];
    if (idx < 6144) {
        int oc = idx / 192, k = idx % 192;
        g_w1p[k * 32 + oc] = W1[idx];
    }
    if (idx < 32768) {
        int oc = idx >> 9, k = idx & 511;
        g_w2p[k * 64 + oc] = W2[idx];
    }
    if (idx < 36864) {
        int oc = idx / 576, k = idx % 576;
        g_w3p[k * 64 + oc] = W3[idx];
    }
}

// ----------------------------------------------------------------------------
// one-hot columns of xs (cols 512..516)
// ----------------------------------------------------------------------------
__global__ void onehot_kernel(const int* __restrict__ la) {
    int r = blockIdx.x * blockDim.x + threadIdx.x;
    if (r < TBn) {
        int a = la[r];
        float* p = g_xs + r * 517 + 512;
#pragma unroll
        for (int j = 0; j < 5; j++) p[j] = (j == a) ? 1.0f : 0.0f;
    }
}

// ----------------------------------------------------------------------------
// conv1: in (TB,3,84,84)/255, W (32,3,8,8) stride4 -> (TB,32,20,20) relu
// 2 images/block, 640 threads. Thread = (img, oy, quarter, ocg):
//   computes 8 oc x 5 px (quarter of an output row). Weights via LDG from
//   pre-packed g_w1p (L1/L2 resident); image rows from smem (broadcast).
// ----------------------------------------------------------------------------
__global__ void __launch_bounds__(640, 1)
conv1_kernel(const float* __restrict__ img, const float* __restrict__ b1) {
    extern __shared__ float sm[];            // 2 * 21168 floats
    int tid = threadIdx.x;
    // stage both images (contiguous), scaled by 1/255
    {
        const float4* g4 = reinterpret_cast<const float4*>(img + blockIdx.x * 2 * 21168);
        float4* s4 = reinterpret_cast<float4*>(sm);
        for (int i = tid; i < 10584; i += 640) {
            float4 v = g4[i];
            v.x *= (1.0f / 255.0f); v.y *= (1.0f / 255.0f);
            v.z *= (1.0f / 255.0f); v.w *= (1.0f / 255.0f);
            s4[i] = v;
        }
    }
    __syncthreads();

    int im = tid / 320, r = tid % 320;
    int oy = r >> 4, q = (r >> 2) & 3, ocg = r & 3;   // q: 5-px quarter, ocg: 8 oc
    const float* ims = sm + im * 21168;
    const float4* w4 = reinterpret_cast<const float4*>(g_w1p);

    float acc[5][8];
#pragma unroll
    for (int p = 0; p < 5; p++)
#pragma unroll
        for (int c = 0; c < 8; c++) acc[p][c] = 0.0f;

    for (int ic = 0; ic < 3; ic++) {
        for (int ky = 0; ky < 8; ky++) {
            const float* row = ims + ic * 7056 + (oy * 4 + ky) * 84 + q * 20;
            float rr[24];
#pragma unroll
            for (int v = 0; v < 6; v++) {
                float4 t = *reinterpret_cast<const float4*>(row + v * 4);
                rr[v * 4 + 0] = t.x; rr[v * 4 + 1] = t.y;
                rr[v * 4 + 2] = t.z; rr[v * 4 + 3] = t.w;
            }
            int kbase = (ic * 8 + ky) * 8;
#pragma unroll
            for (int kx = 0; kx < 8; kx++) {
                int k = kbase + kx;
                float4 w0 = __ldg(&w4[k * 8 + ocg * 2]);
                float4 w1 = __ldg(&w4[k * 8 + ocg * 2 + 1]);
#pragma unroll
                for (int p = 0; p < 5; p++) {
                    float v = rr[p * 4 + kx];
                    acc[p][0] = fmaf(v, w0.x, acc[p][0]);
                    acc[p][1] = fmaf(v, w0.y, acc[p][1]);
                    acc[p][2] = fmaf(v, w0.z, acc[p][2]);
                    acc[p][3] = fmaf(v, w0.w, acc[p][3]);
                    acc[p][4] = fmaf(v, w1.x, acc[p][4]);
                    acc[p][5] = fmaf(v, w1.y, acc[p][5]);
                    acc[p][6] = fmaf(v, w1.z, acc[p][6]);
                    acc[p][7] = fmaf(v, w1.w, acc[p][7]);
                }
            }
        }
    }
    int n = blockIdx.x * 2 + im;
    float* o = g_x1 + n * 12800;
#pragma unroll
    for (int c = 0; c < 8; c++) {
        int oc = ocg * 8 + c;
        float bb = __ldg(&b1[oc]);
        float* op = o + oc * 400 + oy * 20 + q * 5;
#pragma unroll
        for (int p = 0; p < 5; p++) op[p] = fmaxf(acc[p][c] + bb, 0.0f);
    }
}

// ----------------------------------------------------------------------------
// conv2: (TB,32,20,20) * W(64,32,4,4) s2 -> (TB,64,9,9) relu
// 4 images/block, 288 threads. Thread = (img, oy, ocg): 8 oc x 9 px (full row).
// ----------------------------------------------------------------------------
__global__ void __launch_bounds__(288, 1)
conv2_kernel(const float* __restrict__ b2) {
    extern __shared__ float sm[];            // 4 * 12800 floats
    int tid = threadIdx.x;
    {
        const float4* g4 = reinterpret_cast<const float4*>(g_x1 + blockIdx.x * 4 * 12800);
        float4* s4 = reinterpret_cast<float4*>(sm);
        for (int i = tid; i < 12800; i += 288) s4[i] = g4[i];
    }
    __syncthreads();

    int im = tid / 72, r = tid % 72;
    int oy = r >> 3, ocg = r & 7;
    const float* ims = sm + im * 12800;
    const float4* w4 = reinterpret_cast<const float4*>(g_w2p);

    float acc[9][8];
#pragma unroll
    for (int p = 0; p < 9; p++)
#pragma unroll
        for (int c = 0; c < 8; c++) acc[p][c] = 0.0f;

    for (int ic = 0; ic < 32; ic++) {
#pragma unroll
        for (int ky = 0; ky < 4; ky++) {
            const float* row = ims + ic * 400 + (oy * 2 + ky) * 20;
            float rr[20];
#pragma unroll
            for (int v = 0; v < 5; v++) {
                float4 t = *reinterpret_cast<const float4*>(row + v * 4);
                rr[v * 4 + 0] = t.x; rr[v * 4 + 1] = t.y;
                rr[v * 4 + 2] = t.z; rr[v * 4 + 3] = t.w;
            }
            int kbase = (ic * 4 + ky) * 4;
#pragma unroll
            for (int kx = 0; kx < 4; kx++) {
                int k = kbase + kx;
                float4 w0 = __ldg(&w4[k * 16 + ocg * 2]);
                float4 w1 = __ldg(&w4[k * 16 + ocg * 2 + 1]);
#pragma unroll
                for (int p = 0; p < 9; p++) {
                    float v = rr[p * 2 + kx];
                    acc[p][0] = fmaf(v, w0.x, acc[p][0]);
                    acc[p][1] = fmaf(v, w0.y, acc[p][1]);
                    acc[p][2] = fmaf(v, w0.z, acc[p][2]);
                    acc[p][3] = fmaf(v, w0.w, acc[p][3]);
                    acc[p][4] = fmaf(v, w1.x, acc[p][4]);
                    acc[p][5] = fmaf(v, w1.y, acc[p][5]);
                    acc[p][6] = fmaf(v, w1.z, acc[p][6]);
                    acc[p][7] = fmaf(v, w1.w, acc[p][7]);
                }
            }
        }
    }
    int n = blockIdx.x * 4 + im;
    float* o = g_x2 + n * 5184;
#pragma unroll
    for (int c = 0; c < 8; c++) {
        int oc = ocg * 8 + c;
        float bb = __ldg(&b2[oc]);
        float* op = o + oc * 81 + oy * 9;
#pragma unroll
        for (int p = 0; p < 9; p++) op[p] = fmaxf(acc[p][c] + bb, 0.0f);
    }
}

// ----------------------------------------------------------------------------
// conv3: (TB,64,9,9) * W(64,64,3,3) s1 -> (TB,64,7,7) relu -> flatten
// 8 images/block, 448 threads. Thread = (img, oy, ocg): 8 oc x 7 px.
// ----------------------------------------------------------------------------
__global__ void __launch_bounds__(448, 1)
conv3_kernel(const float* __restrict__ b3) {
    extern __shared__ float sm[];            // 8 * 5184 floats
    int tid = threadIdx.x;
    {
        const float4* g4 = reinterpret_cast<const float4*>(g_x2 + blockIdx.x * 8 * 5184);
        float4* s4 = reinterpret_cast<float4*>(sm);
        for (int i = tid; i < 10368; i += 448) s4[i] = g4[i];
    }
    __syncthreads();

    int im = tid / 56, r = tid % 56;
    int oy = r >> 3, ocg = r & 7;
    const float* ims = sm + im * 5184;
    const float4* w4 = reinterpret_cast<const float4*>(g_w3p);

    float acc[7][8];
#pragma unroll
    for (int p = 0; p < 7; p++)
#pragma unroll
        for (int c = 0; c < 8; c++) acc[p][c] = 0.0f;

    for (int ic = 0; ic < 64; ic++) {
#pragma unroll
        for (int ky = 0; ky < 3; ky++) {
            const float* row = ims + ic * 81 + (oy + ky) * 9;
            float rr[9];
#pragma unroll
            for (int v = 0; v < 9; v++) rr[v] = row[v];   // broadcast across 8 ocg lanes
            int kbase = (ic * 3 + ky) * 3;
#pragma unroll
            for (int kx = 0; kx < 3; kx++) {
                int k = kbase + kx;
                float4 w0 = __ldg(&w4[k * 16 + ocg * 2]);
                float4 w1 = __ldg(&w4[k * 16 + ocg * 2 + 1]);
#pragma unroll
                for (int p = 0; p < 7; p++) {
                    float v = rr[p + kx];
                    acc[p][0] = fmaf(v, w0.x, acc[p][0]);
                    acc[p][1] = fmaf(v, w0.y, acc[p][1]);
                    acc[p][2] = fmaf(v, w0.z, acc[p][2]);
                    acc[p][3] = fmaf(v, w0.w, acc[p][3]);
                    acc[p][4] = fmaf(v, w1.x, acc[p][4]);
                    acc[p][5] = fmaf(v, w1.y, acc[p][5]);
                    acc[p][6] = fmaf(v, w1.z, acc[p][6]);
                    acc[p][7] = fmaf(v, w1.w, acc[p][7]);
                }
            }
        }
    }
    int n = blockIdx.x * 8 + im;
    float* o = g_x3 + n * 3136;
#pragma unroll
    for (int c = 0; c < 8; c++) {
        int oc = ocg * 8 + c;
        float bb = __ldg(&b3[oc]);
        float* op = o + oc * 49 + oy * 7;
#pragma unroll
        for (int p = 0; p < 7; p++) op[p] = fmaxf(acc[p][c] + bb, 0.0f);
    }
}

// ----------------------------------------------------------------------------
// Generic tiled GEMM body: C[M x N] = act(A[M x K] * B[N x K]^T + bias)
// BM=BN=64, BK=16, 256 threads, 4x4 microtile, K-major smem tiles.
// ----------------------------------------------------------------------------
__device__ __forceinline__ void gemm_body(const float* __restrict__ A,
                                          const float* __restrict__ B,
                                          const float* __restrict__ bias,
                                          float* __restrict__ C,
                                          int K, int lda, int ldb, int ldc,
                                          bool relu) {
    __shared__ float As[16][68];
    __shared__ float Bs[16][68];
    int bm = blockIdx.y * 64, bn = blockIdx.x * 64;
    int tid = threadIdx.x;
    int tx = tid & 15, ty = tid >> 4;
    float acc[4][4];
#pragma unroll
    for (int i = 0; i < 4; i++)
#pragma unroll
        for (int j = 0; j < 4; j++) acc[i][j] = 0.0f;

    for (int k0 = 0; k0 < K; k0 += 16) {
        for (int i = tid; i < 64 * 16; i += 256) {
            int m = i >> 4, k = i & 15;
            As[k][m] = (k0 + k < K) ? A[(bm + m) * lda + k0 + k] : 0.0f;
        }
        for (int i = tid; i < 64 * 16; i += 256) {
            int nn = i >> 4, k = i & 15;
            Bs[k][nn] = (k0 + k < K) ? B[(bn + nn) * ldb + k0 + k] : 0.0f;
        }
        __syncthreads();
#pragma unroll
        for (int k = 0; k < 16; k++) {
            float4 av = *reinterpret_cast<const float4*>(&As[k][ty * 4]);
            float4 bv = *reinterpret_cast<const float4*>(&Bs[k][tx * 4]);
            float a_[4] = {av.x, av.y, av.z, av.w};
            float b_[4] = {bv.x, bv.y, bv.z, bv.w};
#pragma unroll
            for (int i = 0; i < 4; i++)
#pragma unroll
                for (int j = 0; j < 4; j++)
                    acc[i][j] = fmaf(a_[i], b_[j], acc[i][j]);
        }
        __syncthreads();
    }
#pragma unroll
    for (int i = 0; i < 4; i++) {
        int row = bm + ty * 4 + i;
#pragma unroll
        for (int j = 0; j < 4; j++) {
            int col = bn + tx * 4 + j;
            float v = acc[i][j] + bias[col];
            if (relu) v = fmaxf(v, 0.0f);
            C[row * ldc + col] = v;
        }
    }
}

// FC: feat = relu(x3 @ Wfc^T + bfc) -> g_xs cols [0,512)
__global__ void gemm_fc_kernel(const float* __restrict__ Wfc,
                               const float* __restrict__ bfc) {
    gemm_body(g_x3, Wfc, bfc, g_xs, 3136, 3136, 3136, 517, true);
}

// pre = xs @ W_ih^T + (b_ih + b_hh) -> g_pre
__global__ void gemm_pre_kernel(const float* __restrict__ W_ih) {
    gemm_body(g_xs, W_ih, g_bsum, g_pre, 517, 517, 517, 1024, false);
}

// ----------------------------------------------------------------------------
// LSTM: 32 blocks (one per batch element), persistent over all 32 timesteps.
// ----------------------------------------------------------------------------
__global__ void lstm_kernel(const float* __restrict__ done,
                            const float* __restrict__ h0,
                            const float* __restrict__ c0,
                            float* __restrict__ hT,
                            float* __restrict__ cT) {
    __shared__ float h_s[256];
    __shared__ float g_s[1024];
    int b = blockIdx.x, u = threadIdx.x;
    h_s[u] = h0[b * 256 + u];
    float c_reg = c0[b * 256 + u];
    const float4* w4 = reinterpret_cast<const float4*>(g_whhT);
    float4* gs4 = reinterpret_cast<float4*>(g_s);
    __syncthreads();

    for (int t = 0; t < 32; t++) {
        float m = 1.0f - __ldg(&done[(t << 5) + b]);
        float hv = h_s[u] * m;
        c_reg *= m;
        h_s[u] = hv;
        __syncthreads();

        float4 a = *reinterpret_cast<const float4*>(g_pre + (((t << 5) + b) << 10) + (u << 2));
#pragma unroll 8
        for (int k = 0; k < 256; k++) {
            float hk = h_s[k];
            float4 w = __ldg(&w4[k * 256 + u]);
            a.x = fmaf(hk, w.x, a.x);
            a.y = fmaf(hk, w.y, a.y);
            a.z = fmaf(hk, w.z, a.z);
            a.w = fmaf(hk, w.w, a.w);
        }
        gs4[u] = a;
        __syncthreads();

        float gi = sigmoidf(g_s[u]);
        float gf = sigmoidf(g_s[256 + u]);
        float gg = tanhf(g_s[512 + u]);
        float go = sigmoidf(g_s[768 + u]);
        c_reg = gf * c_reg + gi * gg;
        float hn = go * tanhf(c_reg);
        g_hs[(((t << 5) + b) << 8) + u] = hn;
        h_s[u] = hn;
        __syncthreads();
    }
    hT[b * 256 + u] = h_s[u];
    cT[b * 256 + u] = c_reg;
}

// ----------------------------------------------------------------------------
// Heads: logits = tanh(h@Wp1^T+bp1)@Wp2^T+bp2 ; v analogous. One block per row.
// ----------------------------------------------------------------------------
__global__ void heads_kernel(const float* __restrict__ bp1,
                             const float* __restrict__ Wp2,
                             const float* __restrict__ bp2,
                             const float* __restrict__ bv1,
                             const float* __restrict__ Wv2,
                             const float* __restrict__ bv2,
                             float* __restrict__ logits,
                             float* __restrict__ vout) {
    __shared__ float h_s[256];
    __shared__ float hp[64];
    __shared__ float hv[64];
    int r = blockIdx.x, t = threadIdx.x;
    h_s[t] = g_hs[r * 256 + t];
    h_s[t + 128] = g_hs[r * 256 + t + 128];
    __syncthreads();

    if (t < 64) {
        float s = bp1[t];
#pragma unroll 8
        for (int k = 0; k < 256; k++) s = fmaf(h_s[k], g_wp1T[k * 64 + t], s);
        hp[t] = tanhf(s);
    } else {
        int j = t - 64;
        float s = bv1[j];
#pragma unroll 8
        for (int k = 0; k < 256; k++) s = fmaf(h_s[k], g_wv1T[k * 64 + j], s);
        hv[j] = tanhf(s);
    }
    __syncthreads();

    if (t < 5) {
        float s = bp2[t];
#pragma unroll
        for (int k = 0; k < 64; k++) s = fmaf(hp[k], Wp2[t * 64 + k], s);
        logits[r * 5 + t] = s;
    }
    if (t == 8) {
        float s = bv2[0];
#pragma unroll
        for (int k = 0; k < 64; k++) s = fmaf(hv[k], Wv2[k], s);
        vout[r] = s;
    }
}

// ----------------------------------------------------------------------------
// Launch
// ----------------------------------------------------------------------------
extern "C" void kernel_launch(void* const* d_in, const int* in_sizes, int n_in,
                              void* d_out, int out_size) {
    const float* image = (const float*)d_in[0];
    const int* la = (const int*)d_in[1];
    const float* done = (const float*)d_in[2];
    const float* h0 = (const float*)d_in[3];
    const float* c0 = (const float*)d_in[4];
    const float* W1 = (const float*)d_in[5];
    const float* b1 = (const float*)d_in[6];
    const float* W2 = (const float*)d_in[7];
    const float* b2 = (const float*)d_in[8];
    const float* W3 = (const float*)d_in[9];
    const float* b3 = (const float*)d_in[10];
    const float* Wfc = (const float*)d_in[11];
    const float* bfc = (const float*)d_in[12];
    const float* W_ih = (const float*)d_in[13];
    const float* W_hh = (const float*)d_in[14];
    const float* b_ih = (const float*)d_in[15];
    const float* b_hh = (const float*)d_in[16];
    const float* Wp1 = (const float*)d_in[17];
    const float* bp1 = (const float*)d_in[18];
    const float* Wp2 = (const float*)d_in[19];
    const float* bp2 = (const float*)d_in[20];
    const float* Wv1 = (const float*)d_in[21];
    const float* bv1 = (const float*)d_in[22];
    const float* Wv2 = (const float*)d_in[23];
    const float* bv2 = (const float*)d_in[24];

    float* out = (float*)d_out;
    float* o_logits = out;           // 5120
    float* o_v = out + 5120;         // 1024
    float* o_hT = out + 6144;        // 8192
    float* o_cT = out + 14336;       // 8192

    const int SMEM1 = 2 * 21168 * 4;    // 169344
    const int SMEM2 = 4 * 12800 * 4;    // 204800
    const int SMEM3 = 8 * 5184 * 4;     // 165888
    cudaFuncSetAttribute(conv1_kernel, cudaFuncAttributeMaxDynamicSharedMemorySize, SMEM1);
    cudaFuncSetAttribute(conv2_kernel, cudaFuncAttributeMaxDynamicSharedMemorySize, SMEM2);
    cudaFuncSetAttribute(conv3_kernel, cudaFuncAttributeMaxDynamicSharedMemorySize, SMEM3);

    prep_kernel<<<1024, 256>>>(W_hh, b_ih, b_hh, Wp1, Wv1, W1, W2, W3);
    conv1_kernel<<<512, 640, SMEM1>>>(image, b1);
    conv2_kernel<<<256, 288, SMEM2>>>(b2);
    conv3_kernel<<<128, 448, SMEM3>>>(b3);
    gemm_fc_kernel<<<dim3(512 / 64, 1024 / 64), 256>>>(Wfc, bfc);
    onehot_kernel<<<4, 256>>>(la);
    gemm_pre_kernel<<<dim3(1024 / 64, 1024 / 64), 256>>>(W_ih);
    lstm_kernel<<<32, 256>>>(done, h0, c0, o_hT, o_cT);
    heads_kernel<<<TBn, 128>>>(bp1, Wp2, bp2, bv1, Wv2, bv2, o_logits, o_v);
}

// round 7
// speedup vs baseline: 1.5955x; 1.2913x over previous
#include <cuda_runtime.h>
#include <math.h>

// ----------------------------------------------------------------------------
// Problem constants
//   T=32, B=32, TB=1024, NA=5, HID=256, FEAT=512, IN_DIM=517, FLAT=3136
// Output layout (22528 floats): logits[1024*5] | v[1024] | hT[32*256] | cT[32*256]
// ----------------------------------------------------------------------------

#define TBn 1024

// Scratch (device globals; no allocation allowed)
__device__ float g_x1[TBn * 32 * 20 * 20];   // conv1 out
__device__ float g_x2[TBn * 64 * 9 * 9];     // conv2 out
__device__ float g_x3[TBn * 3136];           // conv3 out (flatten, C,H,W)
__device__ float g_xs[TBn * 517];            // feat || one-hot
__device__ float g_pre[TBn * 1024];          // x @ W_ih^T + b_ih + b_hh
__device__ float g_whhT[256 * 1024];         // W_hh transposed: [k][4*HID]
__device__ float g_bsum[1024];               // b_ih + b_hh
__device__ float g_wp1T[256 * 64];           // Wp1 transposed [k][64]
__device__ float g_wv1T[256 * 64];           // Wv1 transposed [k][64]
__device__ float g_hs[TBn * 256];            // all h outputs
// Pre-packed conv weights, transposed to [k][oc].
__device__ float g_w1p[192 * 32];            // conv1 W
__device__ float g_w2p[512 * 64];            // conv2 W
__device__ float g_w3p[576 * 64];            // conv3 W

__device__ __forceinline__ float sigmoidf(float x) { return 1.0f / (1.0f + expf(-x)); }

// ----------------------------------------------------------------------------
// prep
// ----------------------------------------------------------------------------
__global__ void prep_kernel(const float* __restrict__ W_hh,
                            const float* __restrict__ b_ih,
                            const float* __restrict__ b_hh,
                            const float* __restrict__ Wp1,
                            const float* __restrict__ Wv1,
                            const float* __restrict__ W1,
                            const float* __restrict__ W2,
                            const float* __restrict__ W3) {
    int idx = blockIdx.x * blockDim.x + threadIdx.x;
    if (idx < 262144) {
        int j = idx >> 8, k = idx & 255;
        g_whhT[k * 1024 + j] = W_hh[idx];
    }
    if (idx < 16384) {
        int j = idx >> 8, k = idx & 255;
        g_wp1T[k * 64 + j] = Wp1[idx];
        g_wv1T[k * 64 + j] = Wv1[idx];
    }
    if (idx < 1024) g_bsum[idx] = b_ih[idx] + b_hh[idx];
    if (idx < 6144) {
        int oc = idx / 192, k = idx % 192;
        g_w1p[k * 32 + oc] = W1[idx];
    }
    if (idx < 32768) {
        int oc = idx >> 9, k = idx & 511;
        g_w2p[k * 64 + oc] = W2[idx];
    }
    if (idx < 36864) {
        int oc = idx / 576, k = idx % 576;
        g_w3p[k * 64 + oc] = W3[idx];
    }
}

// ----------------------------------------------------------------------------
// one-hot columns of xs (cols 512..516)
// ----------------------------------------------------------------------------
__global__ void onehot_kernel(const int* __restrict__ la) {
    int r = blockIdx.x * blockDim.x + threadIdx.x;
    if (r < TBn) {
        int a = la[r];
        float* p = g_xs + r * 517 + 512;
#pragma unroll
        for (int j = 0; j < 5; j++) p[j] = (j == a) ? 1.0f : 0.0f;
    }
}

// ----------------------------------------------------------------------------
// conv1: in (TB,3,84,84)/255, W (32,3,8,8) stride4 -> (TB,32,20,20) relu
// ----------------------------------------------------------------------------
__global__ void __launch_bounds__(640, 1)
conv1_kernel(const float* __restrict__ img, const float* __restrict__ b1) {
    extern __shared__ float sm[];            // 2 * 21168 floats
    int tid = threadIdx.x;
    {
        const float4* g4 = reinterpret_cast<const float4*>(img + blockIdx.x * 2 * 21168);
        float4* s4 = reinterpret_cast<float4*>(sm);
        for (int i = tid; i < 10584; i += 640) {
            float4 v = g4[i];
            v.x *= (1.0f / 255.0f); v.y *= (1.0f / 255.0f);
            v.z *= (1.0f / 255.0f); v.w *= (1.0f / 255.0f);
            s4[i] = v;
        }
    }
    __syncthreads();

    int im = tid / 320, r = tid % 320;
    int oy = r >> 4, q = (r >> 2) & 3, ocg = r & 3;
    const float* ims = sm + im * 21168;
    const float4* w4 = reinterpret_cast<const float4*>(g_w1p);

    float acc[5][8];
#pragma unroll
    for (int p = 0; p < 5; p++)
#pragma unroll
        for (int c = 0; c < 8; c++) acc[p][c] = 0.0f;

    for (int ic = 0; ic < 3; ic++) {
        for (int ky = 0; ky < 8; ky++) {
            const float* row = ims + ic * 7056 + (oy * 4 + ky) * 84 + q * 20;
            float rr[24];
#pragma unroll
            for (int v = 0; v < 6; v++) {
                float4 t = *reinterpret_cast<const float4*>(row + v * 4);
                rr[v * 4 + 0] = t.x; rr[v * 4 + 1] = t.y;
                rr[v * 4 + 2] = t.z; rr[v * 4 + 3] = t.w;
            }
            int kbase = (ic * 8 + ky) * 8;
#pragma unroll
            for (int kx = 0; kx < 8; kx++) {
                int k = kbase + kx;
                float4 w0 = __ldg(&w4[k * 8 + ocg * 2]);
                float4 w1 = __ldg(&w4[k * 8 + ocg * 2 + 1]);
#pragma unroll
                for (int p = 0; p < 5; p++) {
                    float v = rr[p * 4 + kx];
                    acc[p][0] = fmaf(v, w0.x, acc[p][0]);
                    acc[p][1] = fmaf(v, w0.y, acc[p][1]);
                    acc[p][2] = fmaf(v, w0.z, acc[p][2]);
                    acc[p][3] = fmaf(v, w0.w, acc[p][3]);
                    acc[p][4] = fmaf(v, w1.x, acc[p][4]);
                    acc[p][5] = fmaf(v, w1.y, acc[p][5]);
                    acc[p][6] = fmaf(v, w1.z, acc[p][6]);
                    acc[p][7] = fmaf(v, w1.w, acc[p][7]);
                }
            }
        }
    }
    int n = blockIdx.x * 2 + im;
    float* o = g_x1 + n * 12800;
#pragma unroll
    for (int c = 0; c < 8; c++) {
        int oc = ocg * 8 + c;
        float bb = __ldg(&b1[oc]);
        float* op = o + oc * 400 + oy * 20 + q * 5;
#pragma unroll
        for (int p = 0; p < 5; p++) op[p] = fmaxf(acc[p][c] + bb, 0.0f);
    }
}

// ----------------------------------------------------------------------------
// conv2: (TB,32,20,20) * W(64,32,4,4) s2 -> (TB,64,9,9) relu
// ----------------------------------------------------------------------------
__global__ void __launch_bounds__(288, 1)
conv2_kernel(const float* __restrict__ b2) {
    extern __shared__ float sm[];            // 4 * 12800 floats
    int tid = threadIdx.x;
    {
        const float4* g4 = reinterpret_cast<const float4*>(g_x1 + blockIdx.x * 4 * 12800);
        float4* s4 = reinterpret_cast<float4*>(sm);
        for (int i = tid; i < 12800; i += 288) s4[i] = g4[i];
    }
    __syncthreads();

    int im = tid / 72, r = tid % 72;
    int oy = r >> 3, ocg = r & 7;
    const float* ims = sm + im * 12800;
    const float4* w4 = reinterpret_cast<const float4*>(g_w2p);

    float acc[9][8];
#pragma unroll
    for (int p = 0; p < 9; p++)
#pragma unroll
        for (int c = 0; c < 8; c++) acc[p][c] = 0.0f;

    for (int ic = 0; ic < 32; ic++) {
#pragma unroll
        for (int ky = 0; ky < 4; ky++) {
            const float* row = ims + ic * 400 + (oy * 2 + ky) * 20;
            float rr[20];
#pragma unroll
            for (int v = 0; v < 5; v++) {
                float4 t = *reinterpret_cast<const float4*>(row + v * 4);
                rr[v * 4 + 0] = t.x; rr[v * 4 + 1] = t.y;
                rr[v * 4 + 2] = t.z; rr[v * 4 + 3] = t.w;
            }
            int kbase = (ic * 4 + ky) * 4;
#pragma unroll
            for (int kx = 0; kx < 4; kx++) {
                int k = kbase + kx;
                float4 w0 = __ldg(&w4[k * 16 + ocg * 2]);
                float4 w1 = __ldg(&w4[k * 16 + ocg * 2 + 1]);
#pragma unroll
                for (int p = 0; p < 9; p++) {
                    float v = rr[p * 2 + kx];
                    acc[p][0] = fmaf(v, w0.x, acc[p][0]);
                    acc[p][1] = fmaf(v, w0.y, acc[p][1]);
                    acc[p][2] = fmaf(v, w0.z, acc[p][2]);
                    acc[p][3] = fmaf(v, w0.w, acc[p][3]);
                    acc[p][4] = fmaf(v, w1.x, acc[p][4]);
                    acc[p][5] = fmaf(v, w1.y, acc[p][5]);
                    acc[p][6] = fmaf(v, w1.z, acc[p][6]);
                    acc[p][7] = fmaf(v, w1.w, acc[p][7]);
                }
            }
        }
    }
    int n = blockIdx.x * 4 + im;
    float* o = g_x2 + n * 5184;
#pragma unroll
    for (int c = 0; c < 8; c++) {
        int oc = ocg * 8 + c;
        float bb = __ldg(&b2[oc]);
        float* op = o + oc * 81 + oy * 9;
#pragma unroll
        for (int p = 0; p < 9; p++) op[p] = fmaxf(acc[p][c] + bb, 0.0f);
    }
}

// ----------------------------------------------------------------------------
// conv3: (TB,64,9,9) * W(64,64,3,3) s1 -> (TB,64,7,7) relu -> flatten
// ----------------------------------------------------------------------------
__global__ void __launch_bounds__(448, 1)
conv3_kernel(const float* __restrict__ b3) {
    extern __shared__ float sm[];            // 8 * 5184 floats
    int tid = threadIdx.x;
    {
        const float4* g4 = reinterpret_cast<const float4*>(g_x2 + blockIdx.x * 8 * 5184);
        float4* s4 = reinterpret_cast<float4*>(sm);
        for (int i = tid; i < 10368; i += 448) s4[i] = g4[i];
    }
    __syncthreads();

    int im = tid / 56, r = tid % 56;
    int oy = r >> 3, ocg = r & 7;
    const float* ims = sm + im * 5184;
    const float4* w4 = reinterpret_cast<const float4*>(g_w3p);

    float acc[7][8];
#pragma unroll
    for (int p = 0; p < 7; p++)
#pragma unroll
        for (int c = 0; c < 8; c++) acc[p][c] = 0.0f;

    for (int ic = 0; ic < 64; ic++) {
#pragma unroll
        for (int ky = 0; ky < 3; ky++) {
            const float* row = ims + ic * 81 + (oy + ky) * 9;
            float rr[9];
#pragma unroll
            for (int v = 0; v < 9; v++) rr[v] = row[v];
            int kbase = (ic * 3 + ky) * 3;
#pragma unroll
            for (int kx = 0; kx < 3; kx++) {
                int k = kbase + kx;
                float4 w0 = __ldg(&w4[k * 16 + ocg * 2]);
                float4 w1 = __ldg(&w4[k * 16 + ocg * 2 + 1]);
#pragma unroll
                for (int p = 0; p < 7; p++) {
                    float v = rr[p + kx];
                    acc[p][0] = fmaf(v, w0.x, acc[p][0]);
                    acc[p][1] = fmaf(v, w0.y, acc[p][1]);
                    acc[p][2] = fmaf(v, w0.z, acc[p][2]);
                    acc[p][3] = fmaf(v, w0.w, acc[p][3]);
                    acc[p][4] = fmaf(v, w1.x, acc[p][4]);
                    acc[p][5] = fmaf(v, w1.y, acc[p][5]);
                    acc[p][6] = fmaf(v, w1.z, acc[p][6]);
                    acc[p][7] = fmaf(v, w1.w, acc[p][7]);
                }
            }
        }
    }
    int n = blockIdx.x * 8 + im;
    float* o = g_x3 + n * 3136;
#pragma unroll
    for (int c = 0; c < 8; c++) {
        int oc = ocg * 8 + c;
        float bb = __ldg(&b3[oc]);
        float* op = o + oc * 49 + oy * 7;
#pragma unroll
        for (int p = 0; p < 7; p++) op[p] = fmaxf(acc[p][c] + bb, 0.0f);
    }
}

// ----------------------------------------------------------------------------
// Double-buffered tiled GEMM: C[M x N] = act(A[M x K] * B[N x K]^T + bias)
// BM=BN=64, BK=16, 256 threads, 4x4 microtile, register-prefetch ping-pong.
// ----------------------------------------------------------------------------
__device__ __forceinline__ void gemm_body(const float* __restrict__ A,
                                          const float* __restrict__ B,
                                          const float* __restrict__ bias,
                                          float* __restrict__ C,
                                          int K, int lda, int ldb, int ldc,
                                          bool relu) {
    __shared__ float As[2][16][68];
    __shared__ float Bs[2][16][68];
    int bm = blockIdx.y * 64, bn = blockIdx.x * 64;
    int tid = threadIdx.x;
    int tx = tid & 15, ty = tid >> 4;
    // load mapping: lk = k within tile, lm = base row; 4 rows per thread
    int lk = tid & 15, lm = tid >> 4;

    float acc[4][4];
#pragma unroll
    for (int i = 0; i < 4; i++)
#pragma unroll
        for (int j = 0; j < 4; j++) acc[i][j] = 0.0f;

    int ntiles = (K + 15) >> 4;
    float ra[4], rb[4];

    // prologue: load tile 0
    {
        bool kin = lk < K;
#pragma unroll
        for (int i = 0; i < 4; i++) {
            ra[i] = kin ? A[(bm + lm + 16 * i) * lda + lk] : 0.0f;
            rb[i] = kin ? B[(bn + lm + 16 * i) * ldb + lk] : 0.0f;
        }
#pragma unroll
        for (int i = 0; i < 4; i++) {
            As[0][lk][lm + 16 * i] = ra[i];
            Bs[0][lk][lm + 16 * i] = rb[i];
        }
    }
    __syncthreads();

    for (int t = 0; t < ntiles; t++) {
        int buf = t & 1;
        if (t + 1 < ntiles) {
            int k0 = (t + 1) << 4;
            bool kin = (k0 + lk) < K;
#pragma unroll
            for (int i = 0; i < 4; i++) {
                ra[i] = kin ? A[(bm + lm + 16 * i) * lda + k0 + lk] : 0.0f;
                rb[i] = kin ? B[(bn + lm + 16 * i) * ldb + k0 + lk] : 0.0f;
            }
        }
#pragma unroll
        for (int k = 0; k < 16; k++) {
            float4 av = *reinterpret_cast<const float4*>(&As[buf][k][ty * 4]);
            float4 bv = *reinterpret_cast<const float4*>(&Bs[buf][k][tx * 4]);
            float a_[4] = {av.x, av.y, av.z, av.w};
            float b_[4] = {bv.x, bv.y, bv.z, bv.w};
#pragma unroll
            for (int i = 0; i < 4; i++)
#pragma unroll
                for (int j = 0; j < 4; j++)
                    acc[i][j] = fmaf(a_[i], b_[j], acc[i][j]);
        }
        if (t + 1 < ntiles) {
            int nbuf = buf ^ 1;
#pragma unroll
            for (int i = 0; i < 4; i++) {
                As[nbuf][lk][lm + 16 * i] = ra[i];
                Bs[nbuf][lk][lm + 16 * i] = rb[i];
            }
            __syncthreads();
        }
    }
#pragma unroll
    for (int i = 0; i < 4; i++) {
        int row = bm + ty * 4 + i;
#pragma unroll
        for (int j = 0; j < 4; j++) {
            int col = bn + tx * 4 + j;
            float v = acc[i][j] + bias[col];
            if (relu) v = fmaxf(v, 0.0f);
            C[row * ldc + col] = v;
        }
    }
}

// FC: feat = relu(x3 @ Wfc^T + bfc) -> g_xs cols [0,512)
__global__ void __launch_bounds__(256)
gemm_fc_kernel(const float* __restrict__ Wfc, const float* __restrict__ bfc) {
    gemm_body(g_x3, Wfc, bfc, g_xs, 3136, 3136, 3136, 517, true);
}

// pre = xs @ W_ih^T + (b_ih + b_hh) -> g_pre
__global__ void __launch_bounds__(256)
gemm_pre_kernel(const float* __restrict__ W_ih) {
    gemm_body(g_xs, W_ih, g_bsum, g_pre, 517, 517, 517, 1024, false);
}

// ----------------------------------------------------------------------------
// LSTM: 16 blocks, 2 batch elements per block, persistent over 32 timesteps.
// Thread u computes gate-cols 4u..4u+3 for BOTH batch elements: each weight
// float4 is loaded once and used for 8 FMAs. Halves L2 W_hh traffic.
// ----------------------------------------------------------------------------
__global__ void __launch_bounds__(256)
lstm_kernel(const float* __restrict__ done,
            const float* __restrict__ h0,
            const float* __restrict__ c0,
            float* __restrict__ hT,
            float* __restrict__ cT) {
    __shared__ float h_s[2][256];
    __shared__ float g_s[2][1024];
    int b0 = blockIdx.x * 2, b1 = b0 + 1;
    int u = threadIdx.x;
    h_s[0][u] = h0[b0 * 256 + u];
    h_s[1][u] = h0[b1 * 256 + u];
    float c0r = c0[b0 * 256 + u];
    float c1r = c0[b1 * 256 + u];
    const float4* w4 = reinterpret_cast<const float4*>(g_whhT);
    __syncthreads();

    for (int t = 0; t < 32; t++) {
        float m0 = 1.0f - __ldg(&done[(t << 5) + b0]);
        float m1 = 1.0f - __ldg(&done[(t << 5) + b1]);
        float hv0 = h_s[0][u] * m0;
        float hv1 = h_s[1][u] * m1;
        c0r *= m0;
        c1r *= m1;
        h_s[0][u] = hv0;
        h_s[1][u] = hv1;
        __syncthreads();

        float4 a0 = *reinterpret_cast<const float4*>(g_pre + (((t << 5) + b0) << 10) + (u << 2));
        float4 a1 = *reinterpret_cast<const float4*>(g_pre + (((t << 5) + b1) << 10) + (u << 2));
#pragma unroll 8
        for (int k = 0; k < 256; k++) {
            float4 w = __ldg(&w4[k * 256 + u]);
            float h0k = h_s[0][k];
            float h1k = h_s[1][k];
            a0.x = fmaf(h0k, w.x, a0.x);
            a0.y = fmaf(h0k, w.y, a0.y);
            a0.z = fmaf(h0k, w.z, a0.z);
            a0.w = fmaf(h0k, w.w, a0.w);
            a1.x = fmaf(h1k, w.x, a1.x);
            a1.y = fmaf(h1k, w.y, a1.y);
            a1.z = fmaf(h1k, w.z, a1.z);
            a1.w = fmaf(h1k, w.w, a1.w);
        }
        reinterpret_cast<float4*>(g_s[0])[u] = a0;
        reinterpret_cast<float4*>(g_s[1])[u] = a1;
        __syncthreads();

        {
            float gi = sigmoidf(g_s[0][u]);
            float gf = sigmoidf(g_s[0][256 + u]);
            float gg = tanhf(g_s[0][512 + u]);
            float go = sigmoidf(g_s[0][768 + u]);
            c0r = gf * c0r + gi * gg;
            float hn = go * tanhf(c0r);
            g_hs[(((t << 5) + b0) << 8) + u] = hn;
            h_s[0][u] = hn;
        }
        {
            float gi = sigmoidf(g_s[1][u]);
            float gf = sigmoidf(g_s[1][256 + u]);
            float gg = tanhf(g_s[1][512 + u]);
            float go = sigmoidf(g_s[1][768 + u]);
            c1r = gf * c1r + gi * gg;
            float hn = go * tanhf(c1r);
            g_hs[(((t << 5) + b1) << 8) + u] = hn;
            h_s[1][u] = hn;
        }
        __syncthreads();
    }
    hT[b0 * 256 + u] = h_s[0][u];
    hT[b1 * 256 + u] = h_s[1][u];
    cT[b0 * 256 + u] = c0r;
    cT[b1 * 256 + u] = c1r;
}

// ----------------------------------------------------------------------------
// Heads: 8 rows per block; weights loaded once per k, 8 FMAs each.
// ----------------------------------------------------------------------------
__global__ void __launch_bounds__(128)
heads_kernel(const float* __restrict__ bp1,
             const float* __restrict__ Wp2,
             const float* __restrict__ bp2,
             const float* __restrict__ bv1,
             const float* __restrict__ Wv2,
             const float* __restrict__ bv2,
             float* __restrict__ logits,
             float* __restrict__ vout) {
    __shared__ float h_s[8][256];
    __shared__ float hp[8][64];
    __shared__ float hv[8][64];
    int r0 = blockIdx.x * 8, t = threadIdx.x;
    // stage 8 rows of h (8*256 = 2048 floats, 128 threads -> 16 each, float4)
    {
        const float4* g4 = reinterpret_cast<const float4*>(g_hs + r0 * 256);
        float4* s4 = reinterpret_cast<float4*>(&h_s[0][0]);
        for (int i = t; i < 512; i += 128) s4[i] = g4[i];
    }
    __syncthreads();

    if (t < 64) {
        float s[8];
#pragma unroll
        for (int r = 0; r < 8; r++) s[r] = bp1[t];
#pragma unroll 4
        for (int k = 0; k < 256; k++) {
            float w = __ldg(&g_wp1T[k * 64 + t]);
#pragma unroll
            for (int r = 0; r < 8; r++) s[r] = fmaf(h_s[r][k], w, s[r]);
        }
#pragma unroll
        for (int r = 0; r < 8; r++) hp[r][t] = tanhf(s[r]);
    } else {
        int j = t - 64;
        float s[8];
#pragma unroll
        for (int r = 0; r < 8; r++) s[r] = bv1[j];
#pragma unroll 4
        for (int k = 0; k < 256; k++) {
            float w = __ldg(&g_wv1T[k * 64 + j]);
#pragma unroll
            for (int r = 0; r < 8; r++) s[r] = fmaf(h_s[r][k], w, s[r]);
        }
#pragma unroll
        for (int r = 0; r < 8; r++) hv[r][j] = tanhf(s[r]);
    }
    __syncthreads();

    // logits: 8 rows x 5 actions = 40 outputs
    if (t < 40) {
        int r = t / 5, a = t % 5;
        float s = bp2[a];
#pragma unroll
        for (int k = 0; k < 64; k++) s = fmaf(hp[r][k], Wp2[a * 64 + k], s);
        logits[(r0 + r) * 5 + a] = s;
    }
    // value: 8 rows
    if (t >= 64 && t < 72) {
        int r = t - 64;
        float s = bv2[0];
#pragma unroll
        for (int k = 0; k < 64; k++) s = fmaf(hv[r][k], Wv2[k], s);
        vout[r0 + r] = s;
    }
}

// ----------------------------------------------------------------------------
// Launch
// ----------------------------------------------------------------------------
extern "C" void kernel_launch(void* const* d_in, const int* in_sizes, int n_in,
                              void* d_out, int out_size) {
    const float* image = (const float*)d_in[0];
    const int* la = (const int*)d_in[1];
    const float* done = (const float*)d_in[2];
    const float* h0 = (const float*)d_in[3];
    const float* c0 = (const float*)d_in[4];
    const float* W1 = (const float*)d_in[5];
    const float* b1 = (const float*)d_in[6];
    const float* W2 = (const float*)d_in[7];
    const float* b2 = (const float*)d_in[8];
    const float* W3 = (const float*)d_in[9];
    const float* b3 = (const float*)d_in[10];
    const float* Wfc = (const float*)d_in[11];
    const float* bfc = (const float*)d_in[12];
    const float* W_ih = (const float*)d_in[13];
    const float* W_hh = (const float*)d_in[14];
    const float* b_ih = (const float*)d_in[15];
    const float* b_hh = (const float*)d_in[16];
    const float* Wp1 = (const float*)d_in[17];
    const float* bp1 = (const float*)d_in[18];
    const float* Wp2 = (const float*)d_in[19];
    const float* bp2 = (const float*)d_in[20];
    const float* Wv1 = (const float*)d_in[21];
    const float* bv1 = (const float*)d_in[22];
    const float* Wv2 = (const float*)d_in[23];
    const float* bv2 = (const float*)d_in[24];

    float* out = (float*)d_out;
    float* o_logits = out;           // 5120
    float* o_v = out + 5120;         // 1024
    float* o_hT = out + 6144;        // 8192
    float* o_cT = out + 14336;       // 8192

    const int SMEM1 = 2 * 21168 * 4;    // 169344
    const int SMEM2 = 4 * 12800 * 4;    // 204800
    const int SMEM3 = 8 * 5184 * 4;     // 165888
    cudaFuncSetAttribute(conv1_kernel, cudaFuncAttributeMaxDynamicSharedMemorySize, SMEM1);
    cudaFuncSetAttribute(conv2_kernel, cudaFuncAttributeMaxDynamicSharedMemorySize, SMEM2);
    cudaFuncSetAttribute(conv3_kernel, cudaFuncAttributeMaxDynamicSharedMemorySize, SMEM3);

    prep_kernel<<<1024, 256>>>(W_hh, b_ih, b_hh, Wp1, Wv1, W1, W2, W3);
    conv1_kernel<<<512, 640, SMEM1>>>(image, b1);
    conv2_kernel<<<256, 288, SMEM2>>>(b2);
    conv3_kernel<<<128, 448, SMEM3>>>(b3);
    gemm_fc_kernel<<<dim3(512 / 64, 1024 / 64), 256>>>(Wfc, bfc);
    onehot_kernel<<<4, 256>>>(la);
    gemm_pre_kernel<<<dim3(1024 / 64, 1024 / 64), 256>>>(W_ih);
    lstm_kernel<<<16, 256>>>(done, h0, c0, o_hT, o_cT);
    heads_kernel<<<128, 128>>>(bp1, Wp2, bp2, bv1, Wv2, bv2, o_logits, o_v);
}

// round 8
// speedup vs baseline: 1.6764x; 1.0507x over previous
#include <cuda_runtime.h>
#include <math.h>

// ----------------------------------------------------------------------------
// Problem constants
//   T=32, B=32, TB=1024, NA=5, HID=256, FEAT=512, IN_DIM=517 (pad 544), FLAT=3136
// Output layout (22528 floats): logits[1024*5] | v[1024] | hT[32*256] | cT[32*256]
// ----------------------------------------------------------------------------

#define TBn 1024
#define KPAD 544    // padded IN_DIM for tf32 GEMM (multiple of 32)

// Scratch (device globals; no allocation allowed)
__device__ float g_x1[TBn * 32 * 20 * 20];   // conv1 out
__device__ float g_x2[TBn * 64 * 9 * 9];     // conv2 out
__device__ float g_x3[TBn * 3136];           // conv3 out (flatten, C,H,W)
__device__ float g_xs[TBn * KPAD];           // feat || one-hot || zero pad
__device__ float g_pre[TBn * 1024];          // x @ W_ih^T + b_ih + b_hh
__device__ float g_whhT[256 * 1024];         // W_hh transposed: [k][4*HID]
__device__ float g_wihp[1024 * KPAD];        // W_ih zero-padded to KPAD
__device__ float g_bsum[1024];               // b_ih + b_hh
__device__ float g_wp1T[256 * 64];           // Wp1 transposed [k][64]
__device__ float g_wv1T[256 * 64];           // Wv1 transposed [k][64]
__device__ float g_hs[TBn * 256];            // all h outputs
// Pre-packed conv weights, transposed to [k][oc].
__device__ float g_w1p[192 * 32];            // conv1 W
__device__ float g_w2p[512 * 64];            // conv2 W
__device__ float g_w3p[576 * 64];            // conv3 W

__device__ __forceinline__ float sigmoidf(float x) { return 1.0f / (1.0f + expf(-x)); }

__device__ __forceinline__ unsigned f2tf(float f) {
    unsigned u;
    asm("cvt.rna.tf32.f32 %0, %1;" : "=r"(u) : "f"(f));
    return u;
}

// ----------------------------------------------------------------------------
// prep
// ----------------------------------------------------------------------------
__global__ void prep_kernel(const float* __restrict__ W_hh,
                            const float* __restrict__ b_ih,
                            const float* __restrict__ b_hh,
                            const float* __restrict__ Wp1,
                            const float* __restrict__ Wv1,
                            const float* __restrict__ W1,
                            const float* __restrict__ W2,
                            const float* __restrict__ W3,
                            const float* __restrict__ W_ih) {
    int idx = blockIdx.x * blockDim.x + threadIdx.x;
    if (idx < 262144) {
        int j = idx >> 8, k = idx & 255;
        g_whhT[k * 1024 + j] = W_hh[idx];
    }
    if (idx < 16384) {
        int j = idx >> 8, k = idx & 255;
        g_wp1T[k * 64 + j] = Wp1[idx];
        g_wv1T[k * 64 + j] = Wv1[idx];
    }
    if (idx < 1024) g_bsum[idx] = b_ih[idx] + b_hh[idx];
    if (idx < 6144) {
        int oc = idx / 192, k = idx % 192;
        g_w1p[k * 32 + oc] = W1[idx];
    }
    if (idx < 32768) {
        int oc = idx >> 9, k = idx & 511;
        g_w2p[k * 64 + oc] = W2[idx];
    }
    if (idx < 36864) {
        int oc = idx / 576, k = idx % 576;
        g_w3p[k * 64 + oc] = W3[idx];
    }
    if (idx < 1024 * KPAD) {
        int row = idx / KPAD, col = idx % KPAD;
        g_wihp[idx] = (col < 517) ? W_ih[row * 517 + col] : 0.0f;
    }
}

// ----------------------------------------------------------------------------
// one-hot columns of xs (cols 512..516) + zero pad (517..543)
// ----------------------------------------------------------------------------
__global__ void onehot_kernel(const int* __restrict__ la) {
    int r = blockIdx.x * blockDim.x + threadIdx.x;
    if (r < TBn) {
        int a = la[r];
        float* p = g_xs + r * KPAD + 512;
#pragma unroll
        for (int j = 0; j < 5; j++) p[j] = (j == a) ? 1.0f : 0.0f;
#pragma unroll
        for (int j = 5; j < 32; j++) p[j] = 0.0f;
    }
}

// ----------------------------------------------------------------------------
// conv1: in (TB,3,84,84)/255, W (32,3,8,8) stride4 -> (TB,32,20,20) relu
// ----------------------------------------------------------------------------
__global__ void __launch_bounds__(640, 1)
conv1_kernel(const float* __restrict__ img, const float* __restrict__ b1) {
    extern __shared__ float sm[];            // 2 * 21168 floats
    int tid = threadIdx.x;
    {
        const float4* g4 = reinterpret_cast<const float4*>(img + blockIdx.x * 2 * 21168);
        float4* s4 = reinterpret_cast<float4*>(sm);
        for (int i = tid; i < 10584; i += 640) {
            float4 v = g4[i];
            v.x *= (1.0f / 255.0f); v.y *= (1.0f / 255.0f);
            v.z *= (1.0f / 255.0f); v.w *= (1.0f / 255.0f);
            s4[i] = v;
        }
    }
    __syncthreads();

    int im = tid / 320, r = tid % 320;
    int oy = r >> 4, q = (r >> 2) & 3, ocg = r & 3;
    const float* ims = sm + im * 21168;
    const float4* w4 = reinterpret_cast<const float4*>(g_w1p);

    float acc[5][8];
#pragma unroll
    for (int p = 0; p < 5; p++)
#pragma unroll
        for (int c = 0; c < 8; c++) acc[p][c] = 0.0f;

    for (int ic = 0; ic < 3; ic++) {
        for (int ky = 0; ky < 8; ky++) {
            const float* row = ims + ic * 7056 + (oy * 4 + ky) * 84 + q * 20;
            float rr[24];
#pragma unroll
            for (int v = 0; v < 6; v++) {
                float4 t = *reinterpret_cast<const float4*>(row + v * 4);
                rr[v * 4 + 0] = t.x; rr[v * 4 + 1] = t.y;
                rr[v * 4 + 2] = t.z; rr[v * 4 + 3] = t.w;
            }
            int kbase = (ic * 8 + ky) * 8;
#pragma unroll
            for (int kx = 0; kx < 8; kx++) {
                int k = kbase + kx;
                float4 w0 = __ldg(&w4[k * 8 + ocg * 2]);
                float4 w1 = __ldg(&w4[k * 8 + ocg * 2 + 1]);
#pragma unroll
                for (int p = 0; p < 5; p++) {
                    float v = rr[p * 4 + kx];
                    acc[p][0] = fmaf(v, w0.x, acc[p][0]);
                    acc[p][1] = fmaf(v, w0.y, acc[p][1]);
                    acc[p][2] = fmaf(v, w0.z, acc[p][2]);
                    acc[p][3] = fmaf(v, w0.w, acc[p][3]);
                    acc[p][4] = fmaf(v, w1.x, acc[p][4]);
                    acc[p][5] = fmaf(v, w1.y, acc[p][5]);
                    acc[p][6] = fmaf(v, w1.z, acc[p][6]);
                    acc[p][7] = fmaf(v, w1.w, acc[p][7]);
                }
            }
        }
    }
    int n = blockIdx.x * 2 + im;
    float* o = g_x1 + n * 12800;
#pragma unroll
    for (int c = 0; c < 8; c++) {
        int oc = ocg * 8 + c;
        float bb = __ldg(&b1[oc]);
        float* op = o + oc * 400 + oy * 20 + q * 5;
#pragma unroll
        for (int p = 0; p < 5; p++) op[p] = fmaxf(acc[p][c] + bb, 0.0f);
    }
}

// ----------------------------------------------------------------------------
// conv2: (TB,32,20,20) * W(64,32,4,4) s2 -> (TB,64,9,9) relu
// ----------------------------------------------------------------------------
__global__ void __launch_bounds__(288, 1)
conv2_kernel(const float* __restrict__ b2) {
    extern __shared__ float sm[];            // 4 * 12800 floats
    int tid = threadIdx.x;
    {
        const float4* g4 = reinterpret_cast<const float4*>(g_x1 + blockIdx.x * 4 * 12800);
        float4* s4 = reinterpret_cast<float4*>(sm);
        for (int i = tid; i < 12800; i += 288) s4[i] = g4[i];
    }
    __syncthreads();

    int im = tid / 72, r = tid % 72;
    int oy = r >> 3, ocg = r & 7;
    const float* ims = sm + im * 12800;
    const float4* w4 = reinterpret_cast<const float4*>(g_w2p);

    float acc[9][8];
#pragma unroll
    for (int p = 0; p < 9; p++)
#pragma unroll
        for (int c = 0; c < 8; c++) acc[p][c] = 0.0f;

    for (int ic = 0; ic < 32; ic++) {
#pragma unroll
        for (int ky = 0; ky < 4; ky++) {
            const float* row = ims + ic * 400 + (oy * 2 + ky) * 20;
            float rr[20];
#pragma unroll
            for (int v = 0; v < 5; v++) {
                float4 t = *reinterpret_cast<const float4*>(row + v * 4);
                rr[v * 4 + 0] = t.x; rr[v * 4 + 1] = t.y;
                rr[v * 4 + 2] = t.z; rr[v * 4 + 3] = t.w;
            }
            int kbase = (ic * 4 + ky) * 4;
#pragma unroll
            for (int kx = 0; kx < 4; kx++) {
                int k = kbase + kx;
                float4 w0 = __ldg(&w4[k * 16 + ocg * 2]);
                float4 w1 = __ldg(&w4[k * 16 + ocg * 2 + 1]);
#pragma unroll
                for (int p = 0; p < 9; p++) {
                    float v = rr[p * 2 + kx];
                    acc[p][0] = fmaf(v, w0.x, acc[p][0]);
                    acc[p][1] = fmaf(v, w0.y, acc[p][1]);
                    acc[p][2] = fmaf(v, w0.z, acc[p][2]);
                    acc[p][3] = fmaf(v, w0.w, acc[p][3]);
                    acc[p][4] = fmaf(v, w1.x, acc[p][4]);
                    acc[p][5] = fmaf(v, w1.y, acc[p][5]);
                    acc[p][6] = fmaf(v, w1.z, acc[p][6]);
                    acc[p][7] = fmaf(v, w1.w, acc[p][7]);
                }
            }
        }
    }
    int n = blockIdx.x * 4 + im;
    float* o = g_x2 + n * 5184;
#pragma unroll
    for (int c = 0; c < 8; c++) {
        int oc = ocg * 8 + c;
        float bb = __ldg(&b2[oc]);
        float* op = o + oc * 81 + oy * 9;
#pragma unroll
        for (int p = 0; p < 9; p++) op[p] = fmaxf(acc[p][c] + bb, 0.0f);
    }
}

// ----------------------------------------------------------------------------
// conv3: (TB,64,9,9) * W(64,64,3,3) s1 -> (TB,64,7,7) relu -> flatten
// ----------------------------------------------------------------------------
__global__ void __launch_bounds__(448, 1)
conv3_kernel(const float* __restrict__ b3) {
    extern __shared__ float sm[];            // 8 * 5184 floats
    int tid = threadIdx.x;
    {
        const float4* g4 = reinterpret_cast<const float4*>(g_x2 + blockIdx.x * 8 * 5184);
        float4* s4 = reinterpret_cast<float4*>(sm);
        for (int i = tid; i < 10368; i += 448) s4[i] = g4[i];
    }
    __syncthreads();

    int im = tid / 56, r = tid % 56;
    int oy = r >> 3, ocg = r & 7;
    const float* ims = sm + im * 5184;
    const float4* w4 = reinterpret_cast<const float4*>(g_w3p);

    float acc[7][8];
#pragma unroll
    for (int p = 0; p < 7; p++)
#pragma unroll
        for (int c = 0; c < 8; c++) acc[p][c] = 0.0f;

    for (int ic = 0; ic < 64; ic++) {
#pragma unroll
        for (int ky = 0; ky < 3; ky++) {
            const float* row = ims + ic * 81 + (oy + ky) * 9;
            float rr[9];
#pragma unroll
            for (int v = 0; v < 9; v++) rr[v] = row[v];
            int kbase = (ic * 3 + ky) * 3;
#pragma unroll
            for (int kx = 0; kx < 3; kx++) {
                int k = kbase + kx;
                float4 w0 = __ldg(&w4[k * 16 + ocg * 2]);
                float4 w1 = __ldg(&w4[k * 16 + ocg * 2 + 1]);
#pragma unroll
                for (int p = 0; p < 7; p++) {
                    float v = rr[p + kx];
                    acc[p][0] = fmaf(v, w0.x, acc[p][0]);
                    acc[p][1] = fmaf(v, w0.y, acc[p][1]);
                    acc[p][2] = fmaf(v, w0.z, acc[p][2]);
                    acc[p][3] = fmaf(v, w0.w, acc[p][3]);
                    acc[p][4] = fmaf(v, w1.x, acc[p][4]);
                    acc[p][5] = fmaf(v, w1.y, acc[p][5]);
                    acc[p][6] = fmaf(v, w1.z, acc[p][6]);
                    acc[p][7] = fmaf(v, w1.w, acc[p][7]);
                }
            }
        }
    }
    int n = blockIdx.x * 8 + im;
    float* o = g_x3 + n * 3136;
#pragma unroll
    for (int c = 0; c < 8; c++) {
        int oc = ocg * 8 + c;
        float bb = __ldg(&b3[oc]);
        float* op = o + oc * 49 + oy * 7;
#pragma unroll
        for (int p = 0; p < 7; p++) op[p] = fmaxf(acc[p][c] + bb, 0.0f);
    }
}

// ----------------------------------------------------------------------------
// tf32 tensor-core GEMM: C[M x N] = act(A[M x K] * B[N x K]^T + bias)
// BM=BN=64, BK=32, 128 threads (4 warps, 32x32 warp tiles),
// mma.sync.m16n8k8.tf32, double-buffered smem (stride 36: conflict-free frags).
// Requires M%64==0, N%64==0, K%32==0.
// ----------------------------------------------------------------------------
__device__ __forceinline__ void mma_tf32(float* c, const unsigned* a, const unsigned* b) {
    asm volatile(
        "mma.sync.aligned.m16n8k8.row.col.f32.tf32.tf32.f32 "
        "{%0,%1,%2,%3}, {%4,%5,%6,%7}, {%8,%9}, {%0,%1,%2,%3};\n"
        : "+f"(c[0]), "+f"(c[1]), "+f"(c[2]), "+f"(c[3])
        : "r"(a[0]), "r"(a[1]), "r"(a[2]), "r"(a[3]), "r"(b[0]), "r"(b[1]));
}

__device__ __forceinline__ void gemm_tf32(const float* __restrict__ A, int lda,
                                          const float* __restrict__ B, int ldb,
                                          const float* __restrict__ bias,
                                          float* __restrict__ C, int ldc,
                                          int K, bool relu) {
    __shared__ unsigned As[2][64][36];
    __shared__ unsigned Bs[2][64][36];
    int tid = threadIdx.x, lane = tid & 31, warp = tid >> 5;
    int bm = blockIdx.y * 64, bn = blockIdx.x * 64;
    int wm = (warp & 1) << 5, wn = (warp >> 1) << 5;

    float c[2][4][4];
#pragma unroll
    for (int mt = 0; mt < 2; mt++)
#pragma unroll
        for (int nt = 0; nt < 4; nt++)
#pragma unroll
            for (int i = 0; i < 4; i++) c[mt][nt][i] = 0.0f;

    int ntiles = K >> 5;
    float4 pa[4], pb[4];

    // prologue: load chunk 0
#pragma unroll
    for (int i = 0; i < 4; i++) {
        int idx = tid + (i << 7);
        int row = idx >> 3, c4 = (idx & 7) << 2;
        pa[i] = *reinterpret_cast<const float4*>(A + (bm + row) * lda + c4);
        pb[i] = *reinterpret_cast<const float4*>(B + (bn + row) * ldb + c4);
    }
#pragma unroll
    for (int i = 0; i < 4; i++) {
        int idx = tid + (i << 7);
        int row = idx >> 3, c4 = (idx & 7) << 2;
        uint4 ta = {f2tf(pa[i].x), f2tf(pa[i].y), f2tf(pa[i].z), f2tf(pa[i].w)};
        uint4 tb = {f2tf(pb[i].x), f2tf(pb[i].y), f2tf(pb[i].z), f2tf(pb[i].w)};
        *reinterpret_cast<uint4*>(&As[0][row][c4]) = ta;
        *reinterpret_cast<uint4*>(&Bs[0][row][c4]) = tb;
    }
    __syncthreads();

    for (int t = 0; t < ntiles; t++) {
        int buf = t & 1;
        if (t + 1 < ntiles) {
            int k0 = (t + 1) << 5;
#pragma unroll
            for (int i = 0; i < 4; i++) {
                int idx = tid + (i << 7);
                int row = idx >> 3, c4 = (idx & 7) << 2;
                pa[i] = *reinterpret_cast<const float4*>(A + (bm + row) * lda + k0 + c4);
                pb[i] = *reinterpret_cast<const float4*>(B + (bn + row) * ldb + k0 + c4);
            }
        }
        int r = lane >> 2, q = lane & 3;
#pragma unroll
        for (int ks = 0; ks < 4; ks++) {
            unsigned a[2][4], b[4][2];
            int kc = ks << 3;
#pragma unroll
            for (int mt = 0; mt < 2; mt++) {
                int mr = wm + (mt << 4) + r;
                a[mt][0] = As[buf][mr][kc + q];
                a[mt][1] = As[buf][mr + 8][kc + q];
                a[mt][2] = As[buf][mr][kc + q + 4];
                a[mt][3] = As[buf][mr + 8][kc + q + 4];
            }
#pragma unroll
            for (int nt = 0; nt < 4; nt++) {
                int nr = wn + (nt << 3) + r;
                b[nt][0] = Bs[buf][nr][kc + q];
                b[nt][1] = Bs[buf][nr][kc + q + 4];
            }
#pragma unroll
            for (int mt = 0; mt < 2; mt++)
#pragma unroll
                for (int nt = 0; nt < 4; nt++)
                    mma_tf32(c[mt][nt], a[mt], b[nt]);
        }
        if (t + 1 < ntiles) {
            int nbuf = buf ^ 1;
#pragma unroll
            for (int i = 0; i < 4; i++) {
                int idx = tid + (i << 7);
                int row = idx >> 3, c4 = (idx & 7) << 2;
                uint4 ta = {f2tf(pa[i].x), f2tf(pa[i].y), f2tf(pa[i].z), f2tf(pa[i].w)};
                uint4 tb = {f2tf(pb[i].x), f2tf(pb[i].y), f2tf(pb[i].z), f2tf(pb[i].w)};
                *reinterpret_cast<uint4*>(&As[nbuf][row][c4]) = ta;
                *reinterpret_cast<uint4*>(&Bs[nbuf][row][c4]) = tb;
            }
            __syncthreads();
        }
    }

    // epilogue
#pragma unroll
    for (int mt = 0; mt < 2; mt++) {
#pragma unroll
        for (int nt = 0; nt < 4; nt++) {
            int row = bm + wm + (mt << 4) + (lane >> 2);
            int col = bn + wn + (nt << 3) + ((lane & 3) << 1);
            float b0 = bias[col], b1 = bias[col + 1];
            float v0 = c[mt][nt][0] + b0;
            float v1 = c[mt][nt][1] + b1;
            float v2 = c[mt][nt][2] + b0;
            float v3 = c[mt][nt][3] + b1;
            if (relu) {
                v0 = fmaxf(v0, 0.0f); v1 = fmaxf(v1, 0.0f);
                v2 = fmaxf(v2, 0.0f); v3 = fmaxf(v3, 0.0f);
            }
            C[row * ldc + col] = v0;
            C[row * ldc + col + 1] = v1;
            C[(row + 8) * ldc + col] = v2;
            C[(row + 8) * ldc + col + 1] = v3;
        }
    }
}

// FC: feat = relu(x3 @ Wfc^T + bfc) -> g_xs cols [0,512), ldc=KPAD
__global__ void __launch_bounds__(128)
gemm_fc_kernel(const float* __restrict__ Wfc, const float* __restrict__ bfc) {
    gemm_tf32(g_x3, 3136, Wfc, 3136, bfc, g_xs, KPAD, 3136, true);
}

// pre = xs @ W_ih^T + (b_ih + b_hh) -> g_pre (K padded to 544 with zeros)
__global__ void __launch_bounds__(128)
gemm_pre_kernel() {
    gemm_tf32(g_xs, KPAD, g_wihp, KPAD, g_bsum, g_pre, 1024, KPAD, false);
}

// ----------------------------------------------------------------------------
// LSTM: 16 blocks, 2 batch elements per block, persistent over 32 timesteps.
// ----------------------------------------------------------------------------
__global__ void __launch_bounds__(256)
lstm_kernel(const float* __restrict__ done,
            const float* __restrict__ h0,
            const float* __restrict__ c0,
            float* __restrict__ hT,
            float* __restrict__ cT) {
    __shared__ float h_s[2][256];
    __shared__ float g_s[2][1024];
    int b0 = blockIdx.x * 2, b1 = b0 + 1;
    int u = threadIdx.x;
    h_s[0][u] = h0[b0 * 256 + u];
    h_s[1][u] = h0[b1 * 256 + u];
    float c0r = c0[b0 * 256 + u];
    float c1r = c0[b1 * 256 + u];
    const float4* w4 = reinterpret_cast<const float4*>(g_whhT);
    __syncthreads();

    for (int t = 0; t < 32; t++) {
        float m0 = 1.0f - __ldg(&done[(t << 5) + b0]);
        float m1 = 1.0f - __ldg(&done[(t << 5) + b1]);
        float hv0 = h_s[0][u] * m0;
        float hv1 = h_s[1][u] * m1;
        c0r *= m0;
        c1r *= m1;
        h_s[0][u] = hv0;
        h_s[1][u] = hv1;
        __syncthreads();

        float4 a0 = *reinterpret_cast<const float4*>(g_pre + (((t << 5) + b0) << 10) + (u << 2));
        float4 a1 = *reinterpret_cast<const float4*>(g_pre + (((t << 5) + b1) << 10) + (u << 2));
#pragma unroll 8
        for (int k = 0; k < 256; k++) {
            float4 w = __ldg(&w4[k * 256 + u]);
            float h0k = h_s[0][k];
            float h1k = h_s[1][k];
            a0.x = fmaf(h0k, w.x, a0.x);
            a0.y = fmaf(h0k, w.y, a0.y);
            a0.z = fmaf(h0k, w.z, a0.z);
            a0.w = fmaf(h0k, w.w, a0.w);
            a1.x = fmaf(h1k, w.x, a1.x);
            a1.y = fmaf(h1k, w.y, a1.y);
            a1.z = fmaf(h1k, w.z, a1.z);
            a1.w = fmaf(h1k, w.w, a1.w);
        }
        reinterpret_cast<float4*>(g_s[0])[u] = a0;
        reinterpret_cast<float4*>(g_s[1])[u] = a1;
        __syncthreads();

        {
            float gi = sigmoidf(g_s[0][u]);
            float gf = sigmoidf(g_s[0][256 + u]);
            float gg = tanhf(g_s[0][512 + u]);
            float go = sigmoidf(g_s[0][768 + u]);
            c0r = gf * c0r + gi * gg;
            float hn = go * tanhf(c0r);
            g_hs[(((t << 5) + b0) << 8) + u] = hn;
            h_s[0][u] = hn;
        }
        {
            float gi = sigmoidf(g_s[1][u]);
            float gf = sigmoidf(g_s[1][256 + u]);
            float gg = tanhf(g_s[1][512 + u]);
            float go = sigmoidf(g_s[1][768 + u]);
            c1r = gf * c1r + gi * gg;
            float hn = go * tanhf(c1r);
            g_hs[(((t << 5) + b1) << 8) + u] = hn;
            h_s[1][u] = hn;
        }
        __syncthreads();
    }
    hT[b0 * 256 + u] = h_s[0][u];
    hT[b1 * 256 + u] = h_s[1][u];
    cT[b0 * 256 + u] = c0r;
    cT[b1 * 256 + u] = c1r;
}

// ----------------------------------------------------------------------------
// Heads: 8 rows per block; weights loaded once per k, 8 FMAs each.
// ----------------------------------------------------------------------------
__global__ void __launch_bounds__(128)
heads_kernel(const float* __restrict__ bp1,
             const float* __restrict__ Wp2,
             const float* __restrict__ bp2,
             const float* __restrict__ bv1,
             const float* __restrict__ Wv2,
             const float* __restrict__ bv2,
             float* __restrict__ logits,
             float* __restrict__ vout) {
    __shared__ float h_s[8][256];
    __shared__ float hp[8][64];
    __shared__ float hv[8][64];
    int r0 = blockIdx.x * 8, t = threadIdx.x;
    {
        const float4* g4 = reinterpret_cast<const float4*>(g_hs + r0 * 256);
        float4* s4 = reinterpret_cast<float4*>(&h_s[0][0]);
        for (int i = t; i < 512; i += 128) s4[i] = g4[i];
    }
    __syncthreads();

    if (t < 64) {
        float s[8];
#pragma unroll
        for (int r = 0; r < 8; r++) s[r] = bp1[t];
#pragma unroll 4
        for (int k = 0; k < 256; k++) {
            float w = __ldg(&g_wp1T[k * 64 + t]);
#pragma unroll
            for (int r = 0; r < 8; r++) s[r] = fmaf(h_s[r][k], w, s[r]);
        }
#pragma unroll
        for (int r = 0; r < 8; r++) hp[r][t] = tanhf(s[r]);
    } else {
        int j = t - 64;
        float s[8];
#pragma unroll
        for (int r = 0; r < 8; r++) s[r] = bv1[j];
#pragma unroll 4
        for (int k = 0; k < 256; k++) {
            float w = __ldg(&g_wv1T[k * 64 + j]);
#pragma unroll
            for (int r = 0; r < 8; r++) s[r] = fmaf(h_s[r][k], w, s[r]);
        }
#pragma unroll
        for (int r = 0; r < 8; r++) hv[r][j] = tanhf(s[r]);
    }
    __syncthreads();

    if (t < 40) {
        int r = t / 5, a = t % 5;
        float s = bp2[a];
#pragma unroll
        for (int k = 0; k < 64; k++) s = fmaf(hp[r][k], Wp2[a * 64 + k], s);
        logits[(r0 + r) * 5 + a] = s;
    }
    if (t >= 64 && t < 72) {
        int r = t - 64;
        float s = bv2[0];
#pragma unroll
        for (int k = 0; k < 64; k++) s = fmaf(hv[r][k], Wv2[k], s);
        vout[r0 + r] = s;
    }
}

// ----------------------------------------------------------------------------
// Launch
// ----------------------------------------------------------------------------
extern "C" void kernel_launch(void* const* d_in, const int* in_sizes, int n_in,
                              void* d_out, int out_size) {
    const float* image = (const float*)d_in[0];
    const int* la = (const int*)d_in[1];
    const float* done = (const float*)d_in[2];
    const float* h0 = (const float*)d_in[3];
    const float* c0 = (const float*)d_in[4];
    const float* W1 = (const float*)d_in[5];
    const float* b1 = (const float*)d_in[6];
    const float* W2 = (const float*)d_in[7];
    const float* b2 = (const float*)d_in[8];
    const float* W3 = (const float*)d_in[9];
    const float* b3 = (const float*)d_in[10];
    const float* Wfc = (const float*)d_in[11];
    const float* bfc = (const float*)d_in[12];
    const float* W_ih = (const float*)d_in[13];
    const float* W_hh = (const float*)d_in[14];
    const float* b_ih = (const float*)d_in[15];
    const float* b_hh = (const float*)d_in[16];
    const float* Wp1 = (const float*)d_in[17];
    const float* bp1 = (const float*)d_in[18];
    const float* Wp2 = (const float*)d_in[19];
    const float* bp2 = (const float*)d_in[20];
    const float* Wv1 = (const float*)d_in[21];
    const float* bv1 = (const float*)d_in[22];
    const float* Wv2 = (const float*)d_in[23];
    const float* bv2 = (const float*)d_in[24];

    float* out = (float*)d_out;
    float* o_logits = out;           // 5120
    float* o_v = out + 5120;         // 1024
    float* o_hT = out + 6144;        // 8192
    float* o_cT = out + 14336;       // 8192

    const int SMEM1 = 2 * 21168 * 4;    // 169344
    const int SMEM2 = 4 * 12800 * 4;    // 204800
    const int SMEM3 = 8 * 5184 * 4;     // 165888
    cudaFuncSetAttribute(conv1_kernel, cudaFuncAttributeMaxDynamicSharedMemorySize, SMEM1);
    cudaFuncSetAttribute(conv2_kernel, cudaFuncAttributeMaxDynamicSharedMemorySize, SMEM2);
    cudaFuncSetAttribute(conv3_kernel, cudaFuncAttributeMaxDynamicSharedMemorySize, SMEM3);

    prep_kernel<<<2176, 256>>>(W_hh, b_ih, b_hh, Wp1, Wv1, W1, W2, W3, W_ih);
    conv1_kernel<<<512, 640, SMEM1>>>(image, b1);
    conv2_kernel<<<256, 288, SMEM2>>>(b2);
    conv3_kernel<<<128, 448, SMEM3>>>(b3);
    gemm_fc_kernel<<<dim3(512 / 64, 1024 / 64), 128>>>(Wfc, bfc);
    onehot_kernel<<<4, 256>>>(la);
    gemm_pre_kernel<<<dim3(1024 / 64, 1024 / 64), 128>>>();
    lstm_kernel<<<16, 256>>>(done, h0, c0, o_hT, o_cT);
    heads_kernel<<<128, 128>>>(bp1, Wp2, bp2, bv1, Wv2, bv2, o_logits, o_v);
}

// round 9
// speedup vs baseline: 2.4362x; 1.4533x over previous
#include <cuda_runtime.h>
#include <math.h>
#include <stdint.h>

// ----------------------------------------------------------------------------
// Problem constants
//   T=32, B=32, TB=1024, NA=5, HID=256, FEAT=512, IN_DIM=517 (pad 544), FLAT=3136
// Output layout (22528 floats): logits[1024*5] | v[1024] | hT[32*256] | cT[32*256]
// ----------------------------------------------------------------------------

#define TBn 1024
#define KPAD 544    // padded IN_DIM for tf32 GEMM (multiple of 32)

// Scratch (device globals; no allocation allowed)
__device__ float g_x1[TBn * 32 * 20 * 20];   // conv1 out
__device__ float g_x2[TBn * 64 * 9 * 9];     // conv2 out
__device__ float g_x3[TBn * 3136];           // conv3 out (flatten, C,H,W)
__device__ float g_xs[TBn * KPAD];           // feat || one-hot || zero pad
__device__ float g_pre[TBn * 1024];          // x @ W_ih^T + b_ih + b_hh
__device__ float g_whhT[256 * 1024];         // W_hh transposed: [k][4*HID]
__device__ float g_wihp[1024 * KPAD];        // W_ih zero-padded to KPAD
__device__ float g_bsum[1024];               // b_ih + b_hh
__device__ float g_wp1T[256 * 64];           // Wp1 transposed [k][64]
__device__ float g_wv1T[256 * 64];           // Wv1 transposed [k][64]
__device__ float g_hs[TBn * 256];            // all h outputs
// Pre-packed conv weights, transposed to [k][oc].
__device__ float g_w1p[192 * 32];            // conv1 W
__device__ float g_w2p[512 * 64];            // conv2 W
__device__ float g_w3p[576 * 64];            // conv3 W

__device__ __forceinline__ float sigmoidf(float x) { return 1.0f / (1.0f + expf(-x)); }

__device__ __forceinline__ unsigned f2tf(float f) {
    unsigned u;
    asm("cvt.rna.tf32.f32 %0, %1;" : "=r"(u) : "f"(f));
    return u;
}

// ---- cluster / DSMEM helpers ----
__device__ __forceinline__ uint32_t smem_u32(const void* p) {
    uint32_t a;
    asm("{ .reg .u64 t; cvta.to.shared.u64 t, %1; cvt.u32.u64 %0, t; }"
        : "=r"(a) : "l"(p));
    return a;
}
__device__ __forceinline__ uint32_t mapa_rank(uint32_t saddr, uint32_t rank) {
    uint32_t r;
    asm("mapa.shared::cluster.u32 %0, %1, %2;" : "=r"(r) : "r"(saddr), "r"(rank));
    return r;
}
__device__ __forceinline__ void st_cluster_f32(uint32_t addr, float v) {
    asm volatile("st.shared::cluster.f32 [%0], %1;" :: "r"(addr), "f"(v) : "memory");
}
#define CLUSTER_SYNC() do { \
    asm volatile("barrier.cluster.arrive.aligned;" ::: "memory"); \
    asm volatile("barrier.cluster.wait.aligned;" ::: "memory"); \
} while (0)

// ----------------------------------------------------------------------------
// prep
// ----------------------------------------------------------------------------
__global__ void prep_kernel(const float* __restrict__ W_hh,
                            const float* __restrict__ b_ih,
                            const float* __restrict__ b_hh,
                            const float* __restrict__ Wp1,
                            const float* __restrict__ Wv1,
                            const float* __restrict__ W1,
                            const float* __restrict__ W2,
                            const float* __restrict__ W3,
                            const float* __restrict__ W_ih) {
    int idx = blockIdx.x * blockDim.x + threadIdx.x;
    if (idx < 262144) {
        int j = idx >> 8, k = idx & 255;
        g_whhT[k * 1024 + j] = W_hh[idx];
    }
    if (idx < 16384) {
        int j = idx >> 8, k = idx & 255;
        g_wp1T[k * 64 + j] = Wp1[idx];
        g_wv1T[k * 64 + j] = Wv1[idx];
    }
    if (idx < 1024) g_bsum[idx] = b_ih[idx] + b_hh[idx];
    if (idx < 6144) {
        int oc = idx / 192, k = idx % 192;
        g_w1p[k * 32 + oc] = W1[idx];
    }
    if (idx < 32768) {
        int oc = idx >> 9, k = idx & 511;
        g_w2p[k * 64 + oc] = W2[idx];
    }
    if (idx < 36864) {
        int oc = idx / 576, k = idx % 576;
        g_w3p[k * 64 + oc] = W3[idx];
    }
    if (idx < 1024 * KPAD) {
        int row = idx / KPAD, col = idx % KPAD;
        g_wihp[idx] = (col < 517) ? W_ih[row * 517 + col] : 0.0f;
    }
}

// ----------------------------------------------------------------------------
// one-hot columns of xs (cols 512..516) + zero pad (517..543)
// ----------------------------------------------------------------------------
__global__ void onehot_kernel(const int* __restrict__ la) {
    int r = blockIdx.x * blockDim.x + threadIdx.x;
    if (r < TBn) {
        int a = la[r];
        float* p = g_xs + r * KPAD + 512;
#pragma unroll
        for (int j = 0; j < 5; j++) p[j] = (j == a) ? 1.0f : 0.0f;
#pragma unroll
        for (int j = 5; j < 32; j++) p[j] = 0.0f;
    }
}

// ----------------------------------------------------------------------------
// conv1: in (TB,3,84,84)/255, W (32,3,8,8) stride4 -> (TB,32,20,20) relu
// ----------------------------------------------------------------------------
__global__ void __launch_bounds__(640, 1)
conv1_kernel(const float* __restrict__ img, const float* __restrict__ b1) {
    extern __shared__ float sm[];            // 2 * 21168 floats
    int tid = threadIdx.x;
    {
        const float4* g4 = reinterpret_cast<const float4*>(img + blockIdx.x * 2 * 21168);
        float4* s4 = reinterpret_cast<float4*>(sm);
        for (int i = tid; i < 10584; i += 640) {
            float4 v = g4[i];
            v.x *= (1.0f / 255.0f); v.y *= (1.0f / 255.0f);
            v.z *= (1.0f / 255.0f); v.w *= (1.0f / 255.0f);
            s4[i] = v;
        }
    }
    __syncthreads();

    int im = tid / 320, r = tid % 320;
    int oy = r >> 4, q = (r >> 2) & 3, ocg = r & 3;
    const float* ims = sm + im * 21168;
    const float4* w4 = reinterpret_cast<const float4*>(g_w1p);

    float acc[5][8];
#pragma unroll
    for (int p = 0; p < 5; p++)
#pragma unroll
        for (int c = 0; c < 8; c++) acc[p][c] = 0.0f;

    for (int ic = 0; ic < 3; ic++) {
        for (int ky = 0; ky < 8; ky++) {
            const float* row = ims + ic * 7056 + (oy * 4 + ky) * 84 + q * 20;
            float rr[24];
#pragma unroll
            for (int v = 0; v < 6; v++) {
                float4 t = *reinterpret_cast<const float4*>(row + v * 4);
                rr[v * 4 + 0] = t.x; rr[v * 4 + 1] = t.y;
                rr[v * 4 + 2] = t.z; rr[v * 4 + 3] = t.w;
            }
            int kbase = (ic * 8 + ky) * 8;
#pragma unroll
            for (int kx = 0; kx < 8; kx++) {
                int k = kbase + kx;
                float4 w0 = __ldg(&w4[k * 8 + ocg * 2]);
                float4 w1 = __ldg(&w4[k * 8 + ocg * 2 + 1]);
#pragma unroll
                for (int p = 0; p < 5; p++) {
                    float v = rr[p * 4 + kx];
                    acc[p][0] = fmaf(v, w0.x, acc[p][0]);
                    acc[p][1] = fmaf(v, w0.y, acc[p][1]);
                    acc[p][2] = fmaf(v, w0.z, acc[p][2]);
                    acc[p][3] = fmaf(v, w0.w, acc[p][3]);
                    acc[p][4] = fmaf(v, w1.x, acc[p][4]);
                    acc[p][5] = fmaf(v, w1.y, acc[p][5]);
                    acc[p][6] = fmaf(v, w1.z, acc[p][6]);
                    acc[p][7] = fmaf(v, w1.w, acc[p][7]);
                }
            }
        }
    }
    int n = blockIdx.x * 2 + im;
    float* o = g_x1 + n * 12800;
#pragma unroll
    for (int c = 0; c < 8; c++) {
        int oc = ocg * 8 + c;
        float bb = __ldg(&b1[oc]);
        float* op = o + oc * 400 + oy * 20 + q * 5;
#pragma unroll
        for (int p = 0; p < 5; p++) op[p] = fmaxf(acc[p][c] + bb, 0.0f);
    }
}

// ----------------------------------------------------------------------------
// conv2: (TB,32,20,20) * W(64,32,4,4) s2 -> (TB,64,9,9) relu
// ----------------------------------------------------------------------------
__global__ void __launch_bounds__(288, 1)
conv2_kernel(const float* __restrict__ b2) {
    extern __shared__ float sm[];            // 4 * 12800 floats
    int tid = threadIdx.x;
    {
        const float4* g4 = reinterpret_cast<const float4*>(g_x1 + blockIdx.x * 4 * 12800);
        float4* s4 = reinterpret_cast<float4*>(sm);
        for (int i = tid; i < 12800; i += 288) s4[i] = g4[i];
    }
    __syncthreads();

    int im = tid / 72, r = tid % 72;
    int oy = r >> 3, ocg = r & 7;
    const float* ims = sm + im * 12800;
    const float4* w4 = reinterpret_cast<const float4*>(g_w2p);

    float acc[9][8];
#pragma unroll
    for (int p = 0; p < 9; p++)
#pragma unroll
        for (int c = 0; c < 8; c++) acc[p][c] = 0.0f;

    for (int ic = 0; ic < 32; ic++) {
#pragma unroll
        for (int ky = 0; ky < 4; ky++) {
            const float* row = ims + ic * 400 + (oy * 2 + ky) * 20;
            float rr[20];
#pragma unroll
            for (int v = 0; v < 5; v++) {
                float4 t = *reinterpret_cast<const float4*>(row + v * 4);
                rr[v * 4 + 0] = t.x; rr[v * 4 + 1] = t.y;
                rr[v * 4 + 2] = t.z; rr[v * 4 + 3] = t.w;
            }
            int kbase = (ic * 4 + ky) * 4;
#pragma unroll
            for (int kx = 0; kx < 4; kx++) {
                int k = kbase + kx;
                float4 w0 = __ldg(&w4[k * 16 + ocg * 2]);
                float4 w1 = __ldg(&w4[k * 16 + ocg * 2 + 1]);
#pragma unroll
                for (int p = 0; p < 9; p++) {
                    float v = rr[p * 2 + kx];
                    acc[p][0] = fmaf(v, w0.x, acc[p][0]);
                    acc[p][1] = fmaf(v, w0.y, acc[p][1]);
                    acc[p][2] = fmaf(v, w0.z, acc[p][2]);
                    acc[p][3] = fmaf(v, w0.w, acc[p][3]);
                    acc[p][4] = fmaf(v, w1.x, acc[p][4]);
                    acc[p][5] = fmaf(v, w1.y, acc[p][5]);
                    acc[p][6] = fmaf(v, w1.z, acc[p][6]);
                    acc[p][7] = fmaf(v, w1.w, acc[p][7]);
                }
            }
        }
    }
    int n = blockIdx.x * 4 + im;
    float* o = g_x2 + n * 5184;
#pragma unroll
    for (int c = 0; c < 8; c++) {
        int oc = ocg * 8 + c;
        float bb = __ldg(&b2[oc]);
        float* op = o + oc * 81 + oy * 9;
#pragma unroll
        for (int p = 0; p < 9; p++) op[p] = fmaxf(acc[p][c] + bb, 0.0f);
    }
}

// ----------------------------------------------------------------------------
// conv3: (TB,64,9,9) * W(64,64,3,3) s1 -> (TB,64,7,7) relu -> flatten
// ----------------------------------------------------------------------------
__global__ void __launch_bounds__(448, 1)
conv3_kernel(const float* __restrict__ b3) {
    extern __shared__ float sm[];            // 8 * 5184 floats
    int tid = threadIdx.x;
    {
        const float4* g4 = reinterpret_cast<const float4*>(g_x2 + blockIdx.x * 8 * 5184);
        float4* s4 = reinterpret_cast<float4*>(sm);
        for (int i = tid; i < 10368; i += 448) s4[i] = g4[i];
    }
    __syncthreads();

    int im = tid / 56, r = tid % 56;
    int oy = r >> 3, ocg = r & 7;
    const float* ims = sm + im * 5184;
    const float4* w4 = reinterpret_cast<const float4*>(g_w3p);

    float acc[7][8];
#pragma unroll
    for (int p = 0; p < 7; p++)
#pragma unroll
        for (int c = 0; c < 8; c++) acc[p][c] = 0.0f;

    for (int ic = 0; ic < 64; ic++) {
#pragma unroll
        for (int ky = 0; ky < 3; ky++) {
            const float* row = ims + ic * 81 + (oy + ky) * 9;
            float rr[9];
#pragma unroll
            for (int v = 0; v < 9; v++) rr[v] = row[v];
            int kbase = (ic * 3 + ky) * 3;
#pragma unroll
            for (int kx = 0; kx < 3; kx++) {
                int k = kbase + kx;
                float4 w0 = __ldg(&w4[k * 16 + ocg * 2]);
                float4 w1 = __ldg(&w4[k * 16 + ocg * 2 + 1]);
#pragma unroll
                for (int p = 0; p < 7; p++) {
                    float v = rr[p + kx];
                    acc[p][0] = fmaf(v, w0.x, acc[p][0]);
                    acc[p][1] = fmaf(v, w0.y, acc[p][1]);
                    acc[p][2] = fmaf(v, w0.z, acc[p][2]);
                    acc[p][3] = fmaf(v, w0.w, acc[p][3]);
                    acc[p][4] = fmaf(v, w1.x, acc[p][4]);
                    acc[p][5] = fmaf(v, w1.y, acc[p][5]);
                    acc[p][6] = fmaf(v, w1.z, acc[p][6]);
                    acc[p][7] = fmaf(v, w1.w, acc[p][7]);
                }
            }
        }
    }
    int n = blockIdx.x * 8 + im;
    float* o = g_x3 + n * 3136;
#pragma unroll
    for (int c = 0; c < 8; c++) {
        int oc = ocg * 8 + c;
        float bb = __ldg(&b3[oc]);
        float* op = o + oc * 49 + oy * 7;
#pragma unroll
        for (int p = 0; p < 7; p++) op[p] = fmaxf(acc[p][c] + bb, 0.0f);
    }
}

// ----------------------------------------------------------------------------
// tf32 tensor-core GEMM: C[M x N] = act(A[M x K] * B[N x K]^T + bias)
// ----------------------------------------------------------------------------
__device__ __forceinline__ void mma_tf32(float* c, const unsigned* a, const unsigned* b) {
    asm volatile(
        "mma.sync.aligned.m16n8k8.row.col.f32.tf32.tf32.f32 "
        "{%0,%1,%2,%3}, {%4,%5,%6,%7}, {%8,%9}, {%0,%1,%2,%3};\n"
        : "+f"(c[0]), "+f"(c[1]), "+f"(c[2]), "+f"(c[3])
        : "r"(a[0]), "r"(a[1]), "r"(a[2]), "r"(a[3]), "r"(b[0]), "r"(b[1]));
}

__device__ __forceinline__ void gemm_tf32(const float* __restrict__ A, int lda,
                                          const float* __restrict__ B, int ldb,
                                          const float* __restrict__ bias,
                                          float* __restrict__ C, int ldc,
                                          int K, bool relu) {
    __shared__ unsigned As[2][64][36];
    __shared__ unsigned Bs[2][64][36];
    int tid = threadIdx.x, lane = tid & 31, warp = tid >> 5;
    int bm = blockIdx.y * 64, bn = blockIdx.x * 64;
    int wm = (warp & 1) << 5, wn = (warp >> 1) << 5;

    float c[2][4][4];
#pragma unroll
    for (int mt = 0; mt < 2; mt++)
#pragma unroll
        for (int nt = 0; nt < 4; nt++)
#pragma unroll
            for (int i = 0; i < 4; i++) c[mt][nt][i] = 0.0f;

    int ntiles = K >> 5;
    float4 pa[4], pb[4];

#pragma unroll
    for (int i = 0; i < 4; i++) {
        int idx = tid + (i << 7);
        int row = idx >> 3, c4 = (idx & 7) << 2;
        pa[i] = *reinterpret_cast<const float4*>(A + (bm + row) * lda + c4);
        pb[i] = *reinterpret_cast<const float4*>(B + (bn + row) * ldb + c4);
    }
#pragma unroll
    for (int i = 0; i < 4; i++) {
        int idx = tid + (i << 7);
        int row = idx >> 3, c4 = (idx & 7) << 2;
        uint4 ta = {f2tf(pa[i].x), f2tf(pa[i].y), f2tf(pa[i].z), f2tf(pa[i].w)};
        uint4 tb = {f2tf(pb[i].x), f2tf(pb[i].y), f2tf(pb[i].z), f2tf(pb[i].w)};
        *reinterpret_cast<uint4*>(&As[0][row][c4]) = ta;
        *reinterpret_cast<uint4*>(&Bs[0][row][c4]) = tb;
    }
    __syncthreads();

    for (int t = 0; t < ntiles; t++) {
        int buf = t & 1;
        if (t + 1 < ntiles) {
            int k0 = (t + 1) << 5;
#pragma unroll
            for (int i = 0; i < 4; i++) {
                int idx = tid + (i << 7);
                int row = idx >> 3, c4 = (idx & 7) << 2;
                pa[i] = *reinterpret_cast<const float4*>(A + (bm + row) * lda + k0 + c4);
                pb[i] = *reinterpret_cast<const float4*>(B + (bn + row) * ldb + k0 + c4);
            }
        }
        int r = lane >> 2, q = lane & 3;
#pragma unroll
        for (int ks = 0; ks < 4; ks++) {
            unsigned a[2][4], b[4][2];
            int kc = ks << 3;
#pragma unroll
            for (int mt = 0; mt < 2; mt++) {
                int mr = wm + (mt << 4) + r;
                a[mt][0] = As[buf][mr][kc + q];
                a[mt][1] = As[buf][mr + 8][kc + q];
                a[mt][2] = As[buf][mr][kc + q + 4];
                a[mt][3] = As[buf][mr + 8][kc + q + 4];
            }
#pragma unroll
            for (int nt = 0; nt < 4; nt++) {
                int nr = wn + (nt << 3) + r;
                b[nt][0] = Bs[buf][nr][kc + q];
                b[nt][1] = Bs[buf][nr][kc + q + 4];
            }
#pragma unroll
            for (int mt = 0; mt < 2; mt++)
#pragma unroll
                for (int nt = 0; nt < 4; nt++)
                    mma_tf32(c[mt][nt], a[mt], b[nt]);
        }
        if (t + 1 < ntiles) {
            int nbuf = buf ^ 1;
#pragma unroll
            for (int i = 0; i < 4; i++) {
                int idx = tid + (i << 7);
                int row = idx >> 3, c4 = (idx & 7) << 2;
                uint4 ta = {f2tf(pa[i].x), f2tf(pa[i].y), f2tf(pa[i].z), f2tf(pa[i].w)};
                uint4 tb = {f2tf(pb[i].x), f2tf(pb[i].y), f2tf(pb[i].z), f2tf(pb[i].w)};
                *reinterpret_cast<uint4*>(&As[nbuf][row][c4]) = ta;
                *reinterpret_cast<uint4*>(&Bs[nbuf][row][c4]) = tb;
            }
            __syncthreads();
        }
    }

#pragma unroll
    for (int mt = 0; mt < 2; mt++) {
#pragma unroll
        for (int nt = 0; nt < 4; nt++) {
            int row = bm + wm + (mt << 4) + (lane >> 2);
            int col = bn + wn + (nt << 3) + ((lane & 3) << 1);
            float b0 = bias[col], b1 = bias[col + 1];
            float v0 = c[mt][nt][0] + b0;
            float v1 = c[mt][nt][1] + b1;
            float v2 = c[mt][nt][2] + b0;
            float v3 = c[mt][nt][3] + b1;
            if (relu) {
                v0 = fmaxf(v0, 0.0f); v1 = fmaxf(v1, 0.0f);
                v2 = fmaxf(v2, 0.0f); v3 = fmaxf(v3, 0.0f);
            }
            C[row * ldc + col] = v0;
            C[row * ldc + col + 1] = v1;
            C[(row + 8) * ldc + col] = v2;
            C[(row + 8) * ldc + col + 1] = v3;
        }
    }
}

__global__ void __launch_bounds__(128)
gemm_fc_kernel(const float* __restrict__ Wfc, const float* __restrict__ bfc) {
    gemm_tf32(g_x3, 3136, Wfc, 3136, bfc, g_xs, KPAD, 3136, true);
}

__global__ void __launch_bounds__(128)
gemm_pre_kernel() {
    gemm_tf32(g_xs, KPAD, g_wihp, KPAD, g_bsum, g_pre, 1024, KPAD, false);
}

// ----------------------------------------------------------------------------
// LSTM: 4 clusters x 8 CTAs. Cluster c owns batches 8c..8c+7. CTA rank r holds
// W_hhT columns [128r, 128r+128) in SMEM (128KB, loaded once). Per step:
//  - every CTA computes its 128 gate-cols for all 8 batches from SMEM weights
//  - gate values scattered to unit-owner CTAs via st.shared::cluster
//  - cluster barrier; owners (unit u owned by CTA u>>5) do the pointwise
//    update (c in registers) and broadcast new h to all 8 CTAs; barrier.
// W_hh global traffic: 4MB total (vs ~16GB streaming from L2 before).
// ----------------------------------------------------------------------------
__global__ void __launch_bounds__(256, 1) __cluster_dims__(8, 1, 1)
lstm_kernel(const float* __restrict__ done,
            const float* __restrict__ h0,
            const float* __restrict__ c0,
            float* __restrict__ hT,
            float* __restrict__ cT) {
    extern __shared__ float sm[];
    float* wsl = sm;                    // 256*128 = 32768 floats (weight slice)
    float* h_s = sm + 32768;            // 8*260 = 2080 floats (padded h, full copy)
    float* gbuf = h_s + 2080;           // 4*8*32 = 1024 floats (owned gate values)
    float* m_s = gbuf + 1024;           // 8 floats (masks)

    int tid = threadIdx.x;
    unsigned rank;
    asm("mov.u32 %0, %%cluster_ctarank;" : "=r"(rank));
    int cl = blockIdx.x >> 3;
    int bbase = cl * 8;

    // load weight slice: wsl[k][jl] = g_whhT[k][128*rank + jl]
    {
        const float* src = g_whhT + 128 * (int)rank;
        for (int i = tid; i < 8192; i += 256) {       // 8192 float4
            int k = i >> 5, j4 = (i & 31) << 2;
            *reinterpret_cast<float4*>(&wsl[k * 128 + j4]) =
                *reinterpret_cast<const float4*>(&src[k * 1024 + j4]);
        }
    }
    // init h (full copy for this cluster's 8 batches, padded stride 260)
    for (int i = tid; i < 2048; i += 256) {
        int b = i >> 8, k = i & 255;
        h_s[b * 260 + k] = h0[(bbase + b) * 256 + k];
    }
    // owner state: thread t owns (batch ob, unit 32*rank + os)
    int ob = tid >> 5, os = tid & 31;
    int ou = 32 * (int)rank + os;
    float c_reg = c0[(bbase + ob) * 256 + ou];
    float hn = 0.0f;

    // compute mapping: thread t -> batch b = t&7, col group jg = t>>3 (4 cols)
    int b = tid & 7, jg = tid >> 3;
    int jbase = 4 * jg;
    int gt = (int)rank >> 1;                       // gate type of this col slice
    int ubase = ((128 * (int)rank) & 255) + jbase; // unit index of col cc=0
    uint32_t owner = (uint32_t)(ubase >> 5);       // same owner for the 4 cols
    uint32_t gbuf_a = smem_u32(gbuf);
    uint32_t h_a = smem_u32(h_s);
    uint32_t peer_gbuf = mapa_rank(gbuf_a, owner);
    uint32_t goff = (uint32_t)(((gt * 8 + b) * 32 + (ubase & 31)) * 4);
    uint32_t hpeer[8];
#pragma unroll
    for (int p = 0; p < 8; p++) hpeer[p] = mapa_rank(h_a, (uint32_t)p);
    uint32_t hoff = (uint32_t)((ob * 260 + ou) * 4);

    __syncthreads();
    CLUSTER_SYNC();

    for (int t = 0; t < 32; t++) {
        if (tid < 8) m_s[tid] = 1.0f - __ldg(&done[t * 32 + bbase + tid]);
        __syncthreads();
        // mask h (every CTA masks its replica) and owned c
        for (int i = tid; i < 2048; i += 256) {
            int bb = i >> 8, k = i & 255;
            h_s[bb * 260 + k] *= m_s[bb];
        }
        c_reg *= m_s[ob];
        __syncthreads();

        // gate pre-activations for this CTA's 4 cols x batch b
        int row = (t << 5) + bbase + b;
        float4 a = *reinterpret_cast<const float4*>(
            g_pre + row * 1024 + 128 * (int)rank + jbase);
        float acc0 = a.x, acc1 = a.y, acc2 = a.z, acc3 = a.w;
        const float* hb = h_s + b * 260;
#pragma unroll 8
        for (int k = 0; k < 256; k++) {
            float hv = hb[k];
            float4 w = *reinterpret_cast<const float4*>(&wsl[k * 128 + jbase]);
            acc0 = fmaf(hv, w.x, acc0);
            acc1 = fmaf(hv, w.y, acc1);
            acc2 = fmaf(hv, w.z, acc2);
            acc3 = fmaf(hv, w.w, acc3);
        }
        st_cluster_f32(peer_gbuf + goff, acc0);
        st_cluster_f32(peer_gbuf + goff + 4, acc1);
        st_cluster_f32(peer_gbuf + goff + 8, acc2);
        st_cluster_f32(peer_gbuf + goff + 12, acc3);
        CLUSTER_SYNC();

        // owner pointwise update for (ob, ou)
        {
            float gi = sigmoidf(gbuf[(0 * 8 + ob) * 32 + os]);
            float gf = sigmoidf(gbuf[(1 * 8 + ob) * 32 + os]);
            float gg = tanhf(gbuf[(2 * 8 + ob) * 32 + os]);
            float go = sigmoidf(gbuf[(3 * 8 + ob) * 32 + os]);
            c_reg = gf * c_reg + gi * gg;
            hn = go * tanhf(c_reg);
            g_hs[((t << 5) + bbase + ob) * 256 + ou] = hn;
#pragma unroll
            for (int p = 0; p < 8; p++) st_cluster_f32(hpeer[p] + hoff, hn);
        }
        CLUSTER_SYNC();
    }
    hT[(bbase + ob) * 256 + ou] = hn;
    cT[(bbase + ob) * 256 + ou] = c_reg;
}

// ----------------------------------------------------------------------------
// Heads: 8 rows per block; weights loaded once per k, 8 FMAs each.
// ----------------------------------------------------------------------------
__global__ void __launch_bounds__(128)
heads_kernel(const float* __restrict__ bp1,
             const float* __restrict__ Wp2,
             const float* __restrict__ bp2,
             const float* __restrict__ bv1,
             const float* __restrict__ Wv2,
             const float* __restrict__ bv2,
             float* __restrict__ logits,
             float* __restrict__ vout) {
    __shared__ float h_s[8][256];
    __shared__ float hp[8][64];
    __shared__ float hv[8][64];
    int r0 = blockIdx.x * 8, t = threadIdx.x;
    {
        const float4* g4 = reinterpret_cast<const float4*>(g_hs + r0 * 256);
        float4* s4 = reinterpret_cast<float4*>(&h_s[0][0]);
        for (int i = t; i < 512; i += 128) s4[i] = g4[i];
    }
    __syncthreads();

    if (t < 64) {
        float s[8];
#pragma unroll
        for (int r = 0; r < 8; r++) s[r] = bp1[t];
#pragma unroll 4
        for (int k = 0; k < 256; k++) {
            float w = __ldg(&g_wp1T[k * 64 + t]);
#pragma unroll
            for (int r = 0; r < 8; r++) s[r] = fmaf(h_s[r][k], w, s[r]);
        }
#pragma unroll
        for (int r = 0; r < 8; r++) hp[r][t] = tanhf(s[r]);
    } else {
        int j = t - 64;
        float s[8];
#pragma unroll
        for (int r = 0; r < 8; r++) s[r] = bv1[j];
#pragma unroll 4
        for (int k = 0; k < 256; k++) {
            float w = __ldg(&g_wv1T[k * 64 + j]);
#pragma unroll
            for (int r = 0; r < 8; r++) s[r] = fmaf(h_s[r][k], w, s[r]);
        }
#pragma unroll
        for (int r = 0; r < 8; r++) hv[r][j] = tanhf(s[r]);
    }
    __syncthreads();

    if (t < 40) {
        int r = t / 5, a = t % 5;
        float s = bp2[a];
#pragma unroll
        for (int k = 0; k < 64; k++) s = fmaf(hp[r][k], Wp2[a * 64 + k], s);
        logits[(r0 + r) * 5 + a] = s;
    }
    if (t >= 64 && t < 72) {
        int r = t - 64;
        float s = bv2[0];
#pragma unroll
        for (int k = 0; k < 64; k++) s = fmaf(hv[r][k], Wv2[k], s);
        vout[r0 + r] = s;
    }
}

// ----------------------------------------------------------------------------
// Launch
// ----------------------------------------------------------------------------
extern "C" void kernel_launch(void* const* d_in, const int* in_sizes, int n_in,
                              void* d_out, int out_size) {
    const float* image = (const float*)d_in[0];
    const int* la = (const int*)d_in[1];
    const float* done = (const float*)d_in[2];
    const float* h0 = (const float*)d_in[3];
    const float* c0 = (const float*)d_in[4];
    const float* W1 = (const float*)d_in[5];
    const float* b1 = (const float*)d_in[6];
    const float* W2 = (const float*)d_in[7];
    const float* b2 = (const float*)d_in[8];
    const float* W3 = (const float*)d_in[9];
    const float* b3 = (const float*)d_in[10];
    const float* Wfc = (const float*)d_in[11];
    const float* bfc = (const float*)d_in[12];
    const float* W_ih = (const float*)d_in[13];
    const float* W_hh = (const float*)d_in[14];
    const float* b_ih = (const float*)d_in[15];
    const float* b_hh = (const float*)d_in[16];
    const float* Wp1 = (const float*)d_in[17];
    const float* bp1 = (const float*)d_in[18];
    const float* Wp2 = (const float*)d_in[19];
    const float* bp2 = (const float*)d_in[20];
    const float* Wv1 = (const float*)d_in[21];
    const float* bv1 = (const float*)d_in[22];
    const float* Wv2 = (const float*)d_in[23];
    const float* bv2 = (const float*)d_in[24];

    float* out = (float*)d_out;
    float* o_logits = out;           // 5120
    float* o_v = out + 5120;         // 1024
    float* o_hT = out + 6144;        // 8192
    float* o_cT = out + 14336;       // 8192

    const int SMEM1 = 2 * 21168 * 4;    // 169344
    const int SMEM2 = 4 * 12800 * 4;    // 204800
    const int SMEM3 = 8 * 5184 * 4;     // 165888
    const int SMEML = (32768 + 2080 + 1024 + 8) * 4;  // 143520
    cudaFuncSetAttribute(conv1_kernel, cudaFuncAttributeMaxDynamicSharedMemorySize, SMEM1);
    cudaFuncSetAttribute(conv2_kernel, cudaFuncAttributeMaxDynamicSharedMemorySize, SMEM2);
    cudaFuncSetAttribute(conv3_kernel, cudaFuncAttributeMaxDynamicSharedMemorySize, SMEM3);
    cudaFuncSetAttribute(lstm_kernel, cudaFuncAttributeMaxDynamicSharedMemorySize, SMEML);

    prep_kernel<<<2176, 256>>>(W_hh, b_ih, b_hh, Wp1, Wv1, W1, W2, W3, W_ih);
    conv1_kernel<<<512, 640, SMEM1>>>(image, b1);
    conv2_kernel<<<256, 288, SMEM2>>>(b2);
    conv3_kernel<<<128, 448, SMEM3>>>(b3);
    gemm_fc_kernel<<<dim3(512 / 64, 1024 / 64), 128>>>(Wfc, bfc);
    onehot_kernel<<<4, 256>>>(la);
    gemm_pre_kernel<<<dim3(1024 / 64, 1024 / 64), 128>>>();
    lstm_kernel<<<32, 256, SMEML>>>(done, h0, c0, o_hT, o_cT);
    heads_kernel<<<128, 128>>>(bp1, Wp2, bp2, bv1, Wv2, bv2, o_logits, o_v);
}